// round 1
// baseline (speedup 1.0000x reference)
#include <cuda_runtime.h>
#include <math.h>

#define BB 8
#define NN 1024
#define BN (BB*NN)
#define KNN 20
#define NEG 0.2f
#define EPS 1e-5f

// -------- scratch (device globals; no allocation allowed) --------
__device__ float g_X0[BN*3];          // x transposed (B,N,3)
__device__ float g_yT[BN*128];        // y transposed (B,M,128)
__device__ float g_ynT[BN*128];       // y normalized transposed
__device__ float g_XCAT[BN*512];      // concat of x1|x2|x3|x4 per point
__device__ float g_S[BB*NN*NN];       // score matrices (32MB)
__device__ float g_P[BN*512];         // W1 @ source  (also stage5 pre-BN output)
__device__ float g_Q[BN*256];         // (W2-W1) @ center
__device__ float g_Wc[256*128];       // combined weight W2-W1
__device__ float g_cvec[BN];          // -0.5*|x_j|^2 column bias
__device__ int   g_idx[BN*KNN];       // knn indices
__device__ float g_part[2*256*512];   // BN partial sums
__device__ float g_mean[512];
__device__ float g_istd[512];

// -------- small prep kernels --------
__global__ void transpose_x(const float* __restrict__ x, float* __restrict__ X0) {
    int t = blockIdx.x*blockDim.x + threadIdx.x;
    if (t < BN) {
        int b = t >> 10, n = t & 1023;
        #pragma unroll
        for (int c = 0; c < 3; c++)
            X0[t*3 + c] = x[((size_t)b*3 + c)*NN + n];
    }
}

__global__ void prep_y(const float* __restrict__ y, float* __restrict__ yT,
                       float* __restrict__ ynT) {
    int m = blockIdx.x;            // global point 0..8191
    int b = m >> 10, mm = m & 1023;
    int c = threadIdx.x;           // 128
    float v = y[((size_t)b*128 + c)*NN + mm];
    __shared__ float red[128];
    red[c] = v*v;
    __syncthreads();
    for (int s = 64; s > 0; s >>= 1) {
        if (c < s) red[c] += red[c+s];
        __syncthreads();
    }
    float nrm = sqrtf(red[0]);
    float sc = 1.0f / fmaxf(nrm, 1e-12f);
    yT [(size_t)m*128 + c] = v;
    ynT[(size_t)m*128 + c] = v * sc;
}

__global__ void cvec_kernel(const float* __restrict__ A, int lda, int C,
                            float* __restrict__ cv) {
    int r = blockIdx.x*blockDim.x + threadIdx.x;
    if (r < BN) {
        float s = 0.f;
        for (int c = 0; c < C; c++) {
            float v = A[(size_t)r*lda + c];
            s += v*v;
        }
        cv[r] = -0.5f * s;
    }
}

__global__ void make_wc(const float* __restrict__ w, int O, int C,
                        float* __restrict__ Wc) {
    int e = blockIdx.x*blockDim.x + threadIdx.x;
    if (e < O*C) {
        int o = e / C, c = e % C;
        Wc[e] = w[o*2*C + C + c] - w[o*2*C + c];
    }
}

// -------- generic GEMM: C[r][c] = sum_k A[r][k]*B[c][k] (+ bias[c]) --------
// 64x64 block tile, 64 threads, 8x8 microtile, k-tile 16.
__global__ void gemm64(int Mrows, int Ncols, int K,
                       const float* __restrict__ A, int lda, int sA,
                       const float* __restrict__ Bm, int ldb, int sB,
                       const float* __restrict__ bias, int sBias,
                       float* __restrict__ C, int ldc, int sC) {
    __shared__ float As[16][68];
    __shared__ float Bs[16][68];
    int z = blockIdx.z;
    A  += (size_t)z * sA;
    Bm += (size_t)z * sB;
    C  += (size_t)z * sC;
    const float* bi = bias ? bias + (size_t)z * sBias : nullptr;
    int row0 = blockIdx.y * 64, col0 = blockIdx.x * 64;
    int tid = threadIdx.x;
    int ty = tid >> 3, tx = tid & 7;

    float acc[8][8];
    #pragma unroll
    for (int i = 0; i < 8; i++)
        #pragma unroll
        for (int j = 0; j < 8; j++) acc[i][j] = 0.f;

    for (int k0 = 0; k0 < K; k0 += 16) {
        #pragma unroll
        for (int l = 0; l < 16; l++) {
            int e = tid + l*64;
            int kk = e & 15, r = e >> 4;
            int gk = k0 + kk;
            As[kk][r] = (gk < K) ? A [(size_t)(row0 + r)*lda + gk] : 0.f;
            Bs[kk][r] = (gk < K) ? Bm[(size_t)(col0 + r)*ldb + gk] : 0.f;
        }
        __syncthreads();
        #pragma unroll
        for (int kk = 0; kk < 16; kk++) {
            float a[8], bb[8];
            #pragma unroll
            for (int i = 0; i < 8; i++) a[i]  = As[kk][ty*8 + i];
            #pragma unroll
            for (int j = 0; j < 8; j++) bb[j] = Bs[kk][tx*8 + j];
            #pragma unroll
            for (int i = 0; i < 8; i++)
                #pragma unroll
                for (int j = 0; j < 8; j++)
                    acc[i][j] = fmaf(a[i], bb[j], acc[i][j]);
        }
        __syncthreads();
    }
    #pragma unroll
    for (int i = 0; i < 8; i++) {
        int r = row0 + ty*8 + i;
        #pragma unroll
        for (int j = 0; j < 8; j++) {
            int c = col0 + tx*8 + j;
            float v = acc[i][j];
            if (bi) v += bi[c];
            C[(size_t)r*ldc + c] = v;
        }
    }
}

// -------- per-row top-K (thread per row) --------
__global__ void topk_kernel(const float* __restrict__ S, int* __restrict__ out) {
    int r = blockIdx.x*blockDim.x + threadIdx.x;
    if (r >= BN) return;
    const float* row = S + (size_t)r * NN;
    float vals[KNN]; int ids[KNN];
    #pragma unroll
    for (int k = 0; k < KNN; k++) { vals[k] = row[k]; ids[k] = k; }
    float mn = vals[0]; int mp = 0;
    #pragma unroll
    for (int k = 1; k < KNN; k++) if (vals[k] < mn) { mn = vals[k]; mp = k; }
    for (int j = KNN; j < NN; j++) {
        float v = row[j];
        if (v > mn) {
            vals[mp] = v; ids[mp] = j;
            mn = vals[0]; mp = 0;
            #pragma unroll
            for (int k = 1; k < KNN; k++) if (vals[k] < mn) { mn = vals[k]; mp = k; }
        }
    }
    #pragma unroll
    for (int k = 0; k < KNN; k++) out[(size_t)r*KNN + k] = ids[k];
}

// -------- BN statistics over gathered edge features --------
// grid (32, B), blockDim = O. v = P[b*NN+idx] + Q[b*NN+i]
__global__ void stats_edge(const float* __restrict__ P, const float* __restrict__ Q,
                           const int* __restrict__ idx, int O,
                           float* __restrict__ part) {
    __shared__ int sIdx[32*KNN];
    int b = blockIdx.y, i0 = blockIdx.x * 32;
    for (int e = threadIdx.x; e < 32*KNN; e += blockDim.x)
        sIdx[e] = idx[(size_t)(b*NN + i0)*KNN + e];
    __syncthreads();
    int o = threadIdx.x;
    float s1 = 0.f, s2 = 0.f;
    for (int ii = 0; ii < 32; ii++) {
        int gi = b*NN + i0 + ii;
        float qv = Q[(size_t)gi*O + o];
        #pragma unroll 4
        for (int k = 0; k < KNN; k++) {
            int j = sIdx[ii*KNN + k];
            float v = P[(size_t)(b*NN + j)*O + o] + qv;
            s1 += v; s2 += v*v;
        }
    }
    int grp = blockIdx.y * gridDim.x + blockIdx.x;   // < 256
    part[(size_t)grp*O + o]        = s1;
    part[(size_t)(256 + grp)*O + o] = s2;
}

__global__ void stats_plain(const float* __restrict__ P, float* __restrict__ part) {
    int b = blockIdx.y, i0 = blockIdx.x * 32;
    int o = threadIdx.x;  // 512
    float s1 = 0.f, s2 = 0.f;
    for (int ii = 0; ii < 32; ii++) {
        float v = P[(size_t)(b*NN + i0 + ii)*512 + o];
        s1 += v; s2 += v*v;
    }
    int grp = blockIdx.y * gridDim.x + blockIdx.x;
    part[(size_t)grp*512 + o]        = s1;
    part[(size_t)(256 + grp)*512 + o] = s2;
}

__global__ void reduce_stats(int O, float cnt, const float* __restrict__ part,
                             float* __restrict__ mean, float* __restrict__ istd) {
    int o = threadIdx.x;
    if (o >= O) return;
    float s1 = 0.f, s2 = 0.f;
    for (int g = 0; g < 256; g++) {
        s1 += part[(size_t)g*O + o];
        s2 += part[(size_t)(256 + g)*O + o];
    }
    float m = s1 / cnt;
    float var = s2 / cnt - m*m;
    mean[o] = m;
    istd[o] = rsqrtf(var + EPS);
}

// -------- fused normalize + lrelu + max-pool over K, write into XCAT slice --------
__global__ void finalize_edge(const float* __restrict__ P, const float* __restrict__ Q,
                              const int* __restrict__ idx, int O, int choff,
                              const float* __restrict__ ga, const float* __restrict__ be,
                              const float* __restrict__ mean, const float* __restrict__ istd,
                              float* __restrict__ XCAT) {
    __shared__ int sIdx[32*KNN];
    int b = blockIdx.y, i0 = blockIdx.x * 32;
    for (int e = threadIdx.x; e < 32*KNN; e += blockDim.x)
        sIdx[e] = idx[(size_t)(b*NN + i0)*KNN + e];
    __syncthreads();
    int o = threadIdx.x;
    float m = mean[o], is = istd[o], g = ga[o], bb = be[o];
    for (int ii = 0; ii < 32; ii++) {
        int gi = b*NN + i0 + ii;
        float qv = Q[(size_t)gi*O + o];
        float mx = -1e30f;
        #pragma unroll 4
        for (int k = 0; k < KNN; k++) {
            int j = sIdx[ii*KNN + k];
            float v = P[(size_t)(b*NN + j)*O + o] + qv;
            float z = (v - m)*is*g + bb;
            z = (z >= 0.f) ? z : NEG*z;
            mx = fmaxf(mx, z);
        }
        XCAT[(size_t)gi*512 + choff + o] = mx;
    }
}

// -------- final BN+lrelu with transposed write to d_out (B,512,N) --------
__global__ void finalize5(const float* __restrict__ P,
                          const float* __restrict__ ga, const float* __restrict__ be,
                          const float* __restrict__ mean, const float* __restrict__ istd,
                          float* __restrict__ out) {
    __shared__ float tile[32][33];
    int b = blockIdx.z, o0 = blockIdx.y * 32, n0 = blockIdx.x * 32;
    int tid = threadIdx.x;
    #pragma unroll
    for (int l = 0; l < 4; l++) {
        int e = tid + l*256;
        int nn = e >> 5, oo = e & 31;
        int o = o0 + oo;
        float v = P[(size_t)(b*NN + n0 + nn)*512 + o];
        v = (v - mean[o]) * istd[o] * ga[o] + be[o];
        v = (v >= 0.f) ? v : NEG*v;
        tile[oo][nn] = v;
    }
    __syncthreads();
    #pragma unroll
    for (int l = 0; l < 4; l++) {
        int e = tid + l*256;
        int oo = e >> 5, nn = e & 31;
        out[(size_t)b*512*NN + (size_t)(o0 + oo)*NN + n0 + nn] = tile[oo][nn];
    }
}

extern "C" void kernel_launch(void* const* d_in, const int* in_sizes, int n_in,
                              void* d_out, int out_size) {
    const float* x  = (const float*)d_in[0];
    const float* y  = (const float*)d_in[1];
    const float* w1 = (const float*)d_in[2];
    const float* w2 = (const float*)d_in[3];
    const float* w3 = (const float*)d_in[4];
    const float* w4 = (const float*)d_in[5];
    const float* w5 = (const float*)d_in[6];
    const float* g1 = (const float*)d_in[7];  const float* b1 = (const float*)d_in[8];
    const float* g2 = (const float*)d_in[9];  const float* b2 = (const float*)d_in[10];
    const float* g3 = (const float*)d_in[11]; const float* b3 = (const float*)d_in[12];
    const float* g4 = (const float*)d_in[13]; const float* b4 = (const float*)d_in[14];
    const float* g5 = (const float*)d_in[15]; const float* b5 = (const float*)d_in[16];
    float* out = (float*)d_out;

    float *X0, *yT, *ynT, *XCAT, *S, *P, *Q, *Wc, *cv, *part, *mean, *istd;
    int* idx;
    cudaGetSymbolAddress((void**)&X0,  g_X0);
    cudaGetSymbolAddress((void**)&yT,  g_yT);
    cudaGetSymbolAddress((void**)&ynT, g_ynT);
    cudaGetSymbolAddress((void**)&XCAT,g_XCAT);
    cudaGetSymbolAddress((void**)&S,   g_S);
    cudaGetSymbolAddress((void**)&P,   g_P);
    cudaGetSymbolAddress((void**)&Q,   g_Q);
    cudaGetSymbolAddress((void**)&Wc,  g_Wc);
    cudaGetSymbolAddress((void**)&cv,  g_cvec);
    cudaGetSymbolAddress((void**)&idx, g_idx);
    cudaGetSymbolAddress((void**)&part,g_part);
    cudaGetSymbolAddress((void**)&mean,g_mean);
    cudaGetSymbolAddress((void**)&istd,g_istd);

    transpose_x<<<(BN+255)/256, 256>>>(x, X0);
    prep_y<<<BN, 128>>>(y, yT, ynT);

    // ================= stage 1 : C=3 -> O=64, out slice [0,64) =================
    cvec_kernel<<<32, 256>>>(X0, 3, 3, cv);
    gemm64<<<dim3(16,16,8), 64>>>(NN, NN, 3, X0, 3, NN*3, X0, 3, NN*3,
                                  cv, NN, S, NN, NN*NN);
    topk_kernel<<<32, 256>>>(S, idx);
    make_wc<<<(64*3+255)/256, 256>>>(w1, 64, 3, Wc);
    gemm64<<<dim3(1,128,1), 64>>>(BN, 64, 3, X0, 3, 0, w1, 6, 0, nullptr, 0, P, 64, 0);
    gemm64<<<dim3(1,128,1), 64>>>(BN, 64, 3, X0, 3, 0, Wc, 3, 0, nullptr, 0, Q, 64, 0);
    stats_edge<<<dim3(32,8), 64>>>(P, Q, idx, 64, part);
    reduce_stats<<<1, 64>>>(64, 163840.f, part, mean, istd);
    finalize_edge<<<dim3(32,8), 64>>>(P, Q, idx, 64, 0, g1, b1, mean, istd, XCAT);

    // ================= stage 2 : C=64 (x1 @ off 0) -> O=64, out [64,128) =======
    cvec_kernel<<<32, 256>>>(XCAT, 512, 64, cv);
    gemm64<<<dim3(16,16,8), 64>>>(NN, NN, 64, XCAT, 512, NN*512, XCAT, 512, NN*512,
                                  cv, NN, S, NN, NN*NN);
    topk_kernel<<<32, 256>>>(S, idx);
    make_wc<<<(64*64+255)/256, 256>>>(w2, 64, 64, Wc);
    gemm64<<<dim3(1,128,1), 64>>>(BN, 64, 64, XCAT, 512, 0, w2, 128, 0, nullptr, 0, P, 64, 0);
    gemm64<<<dim3(1,128,1), 64>>>(BN, 64, 64, XCAT, 512, 0, Wc, 64, 0, nullptr, 0, Q, 64, 0);
    stats_edge<<<dim3(32,8), 64>>>(P, Q, idx, 64, part);
    reduce_stats<<<1, 64>>>(64, 163840.f, part, mean, istd);
    finalize_edge<<<dim3(32,8), 64>>>(P, Q, idx, 64, 64, g2, b2, mean, istd, XCAT);

    // ================= stage 3 : C=64 (x2 @ off 64) -> O=128, out [128,256) ====
    cvec_kernel<<<32, 256>>>(XCAT + 64, 512, 64, cv);
    gemm64<<<dim3(16,16,8), 64>>>(NN, NN, 64, XCAT + 64, 512, NN*512, XCAT + 64, 512, NN*512,
                                  cv, NN, S, NN, NN*NN);
    topk_kernel<<<32, 256>>>(S, idx);
    make_wc<<<(128*64+255)/256, 256>>>(w3, 128, 64, Wc);
    gemm64<<<dim3(2,128,1), 64>>>(BN, 128, 64, XCAT + 64, 512, 0, w3, 128, 0, nullptr, 0, P, 128, 0);
    gemm64<<<dim3(2,128,1), 64>>>(BN, 128, 64, XCAT + 64, 512, 0, Wc, 64, 0, nullptr, 0, Q, 128, 0);
    stats_edge<<<dim3(32,8), 128>>>(P, Q, idx, 128, part);
    reduce_stats<<<1, 128>>>(128, 163840.f, part, mean, istd);
    finalize_edge<<<dim3(32,8), 128>>>(P, Q, idx, 128, 128, g3, b3, mean, istd, XCAT);

    // ===== stage 4 : center x3 (C=128 @ off 128), source y -> O=256, out [256,512)
    gemm64<<<dim3(16,16,8), 64>>>(NN, NN, 128, XCAT + 128, 512, NN*512, ynT, 128, NN*128,
                                  nullptr, 0, S, NN, NN*NN);
    topk_kernel<<<32, 256>>>(S, idx);
    make_wc<<<(256*128+255)/256, 256>>>(w4, 256, 128, Wc);
    gemm64<<<dim3(4,128,1), 64>>>(BN, 256, 128, yT, 128, 0, w4, 256, 0, nullptr, 0, P, 256, 0);
    gemm64<<<dim3(4,128,1), 64>>>(BN, 256, 128, XCAT + 128, 512, 0, Wc, 128, 0, nullptr, 0, Q, 256, 0);
    stats_edge<<<dim3(32,8), 256>>>(P, Q, idx, 256, part);
    reduce_stats<<<1, 256>>>(256, 163840.f, part, mean, istd);
    finalize_edge<<<dim3(32,8), 256>>>(P, Q, idx, 256, 256, g4, b4, mean, istd, XCAT);

    // ================= stage 5 : 512 -> 512, BN over (B,N), write d_out ========
    gemm64<<<dim3(8,128,1), 64>>>(BN, 512, 512, XCAT, 512, 0, w5, 512, 0, nullptr, 0, P, 512, 0);
    stats_plain<<<dim3(32,8), 512>>>(P, part);
    reduce_stats<<<1, 512>>>(512, 8192.f, part, mean, istd);
    finalize5<<<dim3(32,16,8), 256>>>(P, g5, b5, mean, istd, out);
}

// round 2
// speedup vs baseline: 2.9045x; 2.9045x over previous
#include <cuda_runtime.h>
#include <math.h>

#define BB 8
#define NN 1024
#define BN (BB*NN)
#define KNN 20
#define NEG 0.2f
#define EPS 1e-5f

// -------- scratch (device globals; no allocation allowed) --------
__device__ float g_X0[BN*3];          // x transposed (B,N,3)
__device__ float g_yT[BN*128];        // y transposed (B,M,128)
__device__ float g_ynT[BN*128];       // y normalized transposed
__device__ float g_XCAT[BN*512];      // concat of x1|x2|x3|x4 per point
__device__ float g_S[BB*NN*NN];       // score matrices (32MB)
__device__ float g_P[BN*512];         // PQ / stage5 pre-BN output
__device__ float g_Q[BN*256];         // stage4 Q
__device__ float g_Wc[512*128];       // stacked / combined weights
__device__ float g_cvec[BN];          // -0.5*|x_j|^2 column bias
__device__ int   g_idx[BN*KNN];       // knn indices
__device__ float g_part[2*256*512];   // BN partial sums
__device__ float g_mean[512];
__device__ float g_istd[512];

// -------- small prep kernels --------
__global__ void transpose_x(const float* __restrict__ x, float* __restrict__ X0) {
    int t = blockIdx.x*blockDim.x + threadIdx.x;
    if (t < BN) {
        int b = t >> 10, n = t & 1023;
        #pragma unroll
        for (int c = 0; c < 3; c++)
            X0[t*3 + c] = x[((size_t)b*3 + c)*NN + n];
    }
}

__global__ void prep_y(const float* __restrict__ y, float* __restrict__ yT,
                       float* __restrict__ ynT) {
    int m = blockIdx.x;            // global point 0..8191
    int b = m >> 10, mm = m & 1023;
    int c = threadIdx.x;           // 128
    float v = y[((size_t)b*128 + c)*NN + mm];
    __shared__ float red[128];
    red[c] = v*v;
    __syncthreads();
    for (int s = 64; s > 0; s >>= 1) {
        if (c < s) red[c] += red[c+s];
        __syncthreads();
    }
    float nrm = sqrtf(red[0]);
    float sc = 1.0f / fmaxf(nrm, 1e-12f);
    yT [(size_t)m*128 + c] = v;
    ynT[(size_t)m*128 + c] = v * sc;
}

__global__ void cvec_kernel(const float* __restrict__ A, int lda, int C,
                            float* __restrict__ cv) {
    int r = blockIdx.x*blockDim.x + threadIdx.x;
    if (r < BN) {
        float s = 0.f;
        for (int c = 0; c < C; c++) {
            float v = A[(size_t)r*lda + c];
            s += v*v;
        }
        cv[r] = -0.5f * s;
    }
}

// stacked weights: rows [0,O) = W1 (first C cols), rows [O,2O) = W2-W1
__global__ void make_wstack(const float* __restrict__ w, int O, int C,
                            float* __restrict__ out) {
    int e = blockIdx.x*blockDim.x + threadIdx.x;
    if (e < 2*O*C) {
        int r = e / C, c = e % C;
        float v;
        if (r < O) v = w[r*2*C + c];
        else { int o = r - O; v = w[o*2*C + C + c] - w[o*2*C + c]; }
        out[e] = v;
    }
}

__global__ void make_wc(const float* __restrict__ w, int O, int C,
                        float* __restrict__ Wc) {
    int e = blockIdx.x*blockDim.x + threadIdx.x;
    if (e < O*C) {
        int o = e / C, c = e % C;
        Wc[e] = w[o*2*C + C + c] - w[o*2*C + c];
    }
}

// -------- GEMM: C[r][c] = sum_k A[r][k]*B[c][k] (+ bias[c]) --------
// 128x128 tile, 256 threads, 8x8 microtile (2x4 rows, 2x4 cols), k-tile 16
__global__ void __launch_bounds__(256)
gemm128(int K,
        const float* __restrict__ A, int lda, int sA,
        const float* __restrict__ Bm, int ldb, int sB,
        const float* __restrict__ bias, int sBias,
        float* __restrict__ C, int ldc, int sC) {
    __shared__ __align__(16) float As[16][132];
    __shared__ __align__(16) float Bs[16][132];
    int z = blockIdx.z;
    A  += (size_t)z * sA;
    Bm += (size_t)z * sB;
    C  += (size_t)z * sC;
    const float* bi = bias ? bias + (size_t)z * sBias : nullptr;
    int row0 = blockIdx.y * 128, col0 = blockIdx.x * 128;
    int tid = threadIdx.x;
    int ty = tid >> 4, tx = tid & 15;

    float acc[8][8];
    #pragma unroll
    for (int i = 0; i < 8; i++)
        #pragma unroll
        for (int j = 0; j < 8; j++) acc[i][j] = 0.f;

    for (int k0 = 0; k0 < K; k0 += 16) {
        #pragma unroll
        for (int l = 0; l < 8; l++) {
            int e = tid + l*256;
            int kk = e & 15, r = e >> 4;
            int gk = k0 + kk;
            As[kk][r] = (gk < K) ? A [(size_t)(row0 + r)*lda + gk] : 0.f;
            Bs[kk][r] = (gk < K) ? Bm[(size_t)(col0 + r)*ldb + gk] : 0.f;
        }
        __syncthreads();
        #pragma unroll
        for (int kk = 0; kk < 16; kk++) {
            float4 a0 = *(const float4*)&As[kk][ty*4];
            float4 a1 = *(const float4*)&As[kk][ty*4 + 64];
            float4 b0 = *(const float4*)&Bs[kk][tx*4];
            float4 b1 = *(const float4*)&Bs[kk][tx*4 + 64];
            float av[8] = {a0.x,a0.y,a0.z,a0.w,a1.x,a1.y,a1.z,a1.w};
            float bv[8] = {b0.x,b0.y,b0.z,b0.w,b1.x,b1.y,b1.z,b1.w};
            #pragma unroll
            for (int i = 0; i < 8; i++)
                #pragma unroll
                for (int j = 0; j < 8; j++)
                    acc[i][j] = fmaf(av[i], bv[j], acc[i][j]);
        }
        __syncthreads();
    }
    #pragma unroll
    for (int i = 0; i < 8; i++) {
        int r = row0 + ((i >> 2) << 6) + ty*4 + (i & 3);
        int c0 = col0 + tx*4;
        int c1 = col0 + 64 + tx*4;
        float4 o0, o1;
        o0.x = acc[i][0]; o0.y = acc[i][1]; o0.z = acc[i][2]; o0.w = acc[i][3];
        o1.x = acc[i][4]; o1.y = acc[i][5]; o1.z = acc[i][6]; o1.w = acc[i][7];
        if (bi) {
            o0.x += bi[c0];   o0.y += bi[c0+1]; o0.z += bi[c0+2]; o0.w += bi[c0+3];
            o1.x += bi[c1];   o1.y += bi[c1+1]; o1.z += bi[c1+2]; o1.w += bi[c1+3];
        }
        *(float4*)&C[(size_t)r*ldc + c0] = o0;
        *(float4*)&C[(size_t)r*ldc + c1] = o1;
    }
}

// -------- per-row top-K: one block per row, coalesced --------
__global__ void __launch_bounds__(256)
topk_block(const float* __restrict__ S, int* __restrict__ out) {
    int r = blockIdx.x;
    int tid = threadIdx.x;
    __shared__ float wv[8];
    __shared__ int   wi[8];
    __shared__ int   swin;
    const float4* s4 = (const float4*)(S + (size_t)r * NN);
    float4 v4 = s4[tid];
    float v[4] = {v4.x, v4.y, v4.z, v4.w};
    int lane = tid & 31, warp = tid >> 5;
    for (int k = 0; k < KNN; k++) {
        float bv = v[0]; int bi = tid*4;
        #pragma unroll
        for (int j = 1; j < 4; j++)
            if (v[j] > bv) { bv = v[j]; bi = tid*4 + j; }
        #pragma unroll
        for (int off = 16; off; off >>= 1) {
            float ov = __shfl_down_sync(0xffffffffu, bv, off);
            int   oi = __shfl_down_sync(0xffffffffu, bi, off);
            if (ov > bv || (ov == bv && oi < bi)) { bv = ov; bi = oi; }
        }
        if (lane == 0) { wv[warp] = bv; wi[warp] = bi; }
        __syncthreads();
        if (tid == 0) {
            float fb = wv[0]; int fi = wi[0];
            #pragma unroll
            for (int w = 1; w < 8; w++)
                if (wv[w] > fb || (wv[w] == fb && wi[w] < fi)) { fb = wv[w]; fi = wi[w]; }
            swin = fi;
            out[(size_t)r*KNN + k] = fi;
        }
        __syncthreads();
        int w = swin;
        if ((w >> 2) == tid) v[w & 3] = -1e30f;
    }
}

// -------- BN statistics over gathered edge features --------
// 256 threads: o = tid & (O-1), point-parallel pp = tid >> oshift
__global__ void __launch_bounds__(256)
stats_edge(const float* __restrict__ P, int ldp,
           const float* __restrict__ Q, int ldq,
           const int* __restrict__ idx, int O, int oshift,
           float* __restrict__ part) {
    __shared__ int sIdx[32*KNN];
    __shared__ float red1[256], red2[256];
    int b = blockIdx.y, i0 = blockIdx.x * 32;
    for (int e = threadIdx.x; e < 32*KNN; e += 256)
        sIdx[e] = idx[(size_t)(b*NN + i0)*KNN + e];
    __syncthreads();
    int o  = threadIdx.x & (O-1);
    int pp = threadIdx.x >> oshift;
    int PP = 256 >> oshift;
    float s1 = 0.f, s2 = 0.f;
    for (int ii = pp; ii < 32; ii += PP) {
        int gi = b*NN + i0 + ii;
        float qv = Q[(size_t)gi*ldq + o];
        #pragma unroll 4
        for (int k = 0; k < KNN; k++) {
            int j = sIdx[ii*KNN + k];
            float pv = P[(size_t)(b*NN + j)*ldp + o];
            float vv = pv + qv;
            s1 += vv; s2 += vv*vv;
        }
    }
    red1[threadIdx.x] = s1; red2[threadIdx.x] = s2;
    __syncthreads();
    if (pp == 0) {
        for (int p = 1; p < PP; p++) { s1 += red1[o + p*O]; s2 += red2[o + p*O]; }
        int grp = blockIdx.y * gridDim.x + blockIdx.x;   // < 256
        part[(size_t)grp*O + o]         = s1;
        part[(size_t)(256 + grp)*O + o] = s2;
    }
}

__global__ void stats_plain(const float* __restrict__ P, float* __restrict__ part) {
    int b = blockIdx.y, i0 = blockIdx.x * 32;
    int o = threadIdx.x;  // 512
    float s1 = 0.f, s2 = 0.f;
    for (int ii = 0; ii < 32; ii++) {
        float v = P[(size_t)(b*NN + i0 + ii)*512 + o];
        s1 += v; s2 += v*v;
    }
    int grp = blockIdx.y * gridDim.x + blockIdx.x;
    part[(size_t)grp*512 + o]         = s1;
    part[(size_t)(256 + grp)*512 + o] = s2;
}

__global__ void reduce_stats(int O, float cnt, const float* __restrict__ part,
                             float* __restrict__ mean, float* __restrict__ istd) {
    int o = threadIdx.x;
    if (o >= O) return;
    float s1 = 0.f, s2 = 0.f;
    for (int g = 0; g < 256; g++) {
        s1 += part[(size_t)g*O + o];
        s2 += part[(size_t)(256 + g)*O + o];
    }
    float m = s1 / cnt;
    float var = s2 / cnt - m*m;
    mean[o] = m;
    istd[o] = rsqrtf(var + EPS);
}

// -------- fused normalize + lrelu + max-pool over K into XCAT slice --------
__global__ void __launch_bounds__(256)
finalize_edge(const float* __restrict__ P, int ldp,
              const float* __restrict__ Q, int ldq,
              const int* __restrict__ idx, int O, int oshift, int choff,
              const float* __restrict__ ga, const float* __restrict__ be,
              const float* __restrict__ mean, const float* __restrict__ istd,
              float* __restrict__ XCAT) {
    __shared__ int sIdx[32*KNN];
    int b = blockIdx.y, i0 = blockIdx.x * 32;
    for (int e = threadIdx.x; e < 32*KNN; e += 256)
        sIdx[e] = idx[(size_t)(b*NN + i0)*KNN + e];
    __syncthreads();
    int o  = threadIdx.x & (O-1);
    int pp = threadIdx.x >> oshift;
    int PP = 256 >> oshift;
    float m = mean[o], is = istd[o], g = ga[o], bb = be[o];
    for (int ii = pp; ii < 32; ii += PP) {
        int gi = b*NN + i0 + ii;
        float qv = Q[(size_t)gi*ldq + o];
        float mx = -1e30f;
        #pragma unroll 4
        for (int k = 0; k < KNN; k++) {
            int j = sIdx[ii*KNN + k];
            float v = P[(size_t)(b*NN + j)*ldp + o] + qv;
            float z = (v - m)*is*g + bb;
            z = (z >= 0.f) ? z : NEG*z;
            mx = fmaxf(mx, z);
        }
        XCAT[(size_t)gi*512 + choff + o] = mx;
    }
}

// -------- final BN+lrelu with transposed write to d_out (B,512,N) --------
__global__ void finalize5(const float* __restrict__ P,
                          const float* __restrict__ ga, const float* __restrict__ be,
                          const float* __restrict__ mean, const float* __restrict__ istd,
                          float* __restrict__ out) {
    __shared__ float tile[32][33];
    int b = blockIdx.z, o0 = blockIdx.y * 32, n0 = blockIdx.x * 32;
    int tid = threadIdx.x;
    #pragma unroll
    for (int l = 0; l < 4; l++) {
        int e = tid + l*256;
        int nn = e >> 5, oo = e & 31;
        int o = o0 + oo;
        float v = P[(size_t)(b*NN + n0 + nn)*512 + o];
        v = (v - mean[o]) * istd[o] * ga[o] + be[o];
        v = (v >= 0.f) ? v : NEG*v;
        tile[oo][nn] = v;
    }
    __syncthreads();
    #pragma unroll
    for (int l = 0; l < 4; l++) {
        int e = tid + l*256;
        int oo = e >> 5, nn = e & 31;
        out[(size_t)b*512*NN + (size_t)(o0 + oo)*NN + n0 + nn] = tile[oo][nn];
    }
}

extern "C" void kernel_launch(void* const* d_in, const int* in_sizes, int n_in,
                              void* d_out, int out_size) {
    const float* x  = (const float*)d_in[0];
    const float* y  = (const float*)d_in[1];
    const float* w1 = (const float*)d_in[2];
    const float* w2 = (const float*)d_in[3];
    const float* w3 = (const float*)d_in[4];
    const float* w4 = (const float*)d_in[5];
    const float* w5 = (const float*)d_in[6];
    const float* g1 = (const float*)d_in[7];  const float* b1 = (const float*)d_in[8];
    const float* g2 = (const float*)d_in[9];  const float* b2 = (const float*)d_in[10];
    const float* g3 = (const float*)d_in[11]; const float* b3 = (const float*)d_in[12];
    const float* g4 = (const float*)d_in[13]; const float* b4 = (const float*)d_in[14];
    const float* g5 = (const float*)d_in[15]; const float* b5 = (const float*)d_in[16];
    float* out = (float*)d_out;

    float *X0, *yT, *ynT, *XCAT, *S, *P, *Q, *Wc, *cv, *part, *mean, *istd;
    int* idx;
    cudaGetSymbolAddress((void**)&X0,  g_X0);
    cudaGetSymbolAddress((void**)&yT,  g_yT);
    cudaGetSymbolAddress((void**)&ynT, g_ynT);
    cudaGetSymbolAddress((void**)&XCAT,g_XCAT);
    cudaGetSymbolAddress((void**)&S,   g_S);
    cudaGetSymbolAddress((void**)&P,   g_P);
    cudaGetSymbolAddress((void**)&Q,   g_Q);
    cudaGetSymbolAddress((void**)&Wc,  g_Wc);
    cudaGetSymbolAddress((void**)&cv,  g_cvec);
    cudaGetSymbolAddress((void**)&idx, g_idx);
    cudaGetSymbolAddress((void**)&part,g_part);
    cudaGetSymbolAddress((void**)&mean,g_mean);
    cudaGetSymbolAddress((void**)&istd,g_istd);

    transpose_x<<<(BN+255)/256, 256>>>(x, X0);
    prep_y<<<BN, 128>>>(y, yT, ynT);

    // ================= stage 1 : C=3 -> O=64, out slice [0,64) =================
    cvec_kernel<<<32, 256>>>(X0, 3, 3, cv);
    gemm128<<<dim3(8,8,8), 256>>>(3, X0, 3, NN*3, X0, 3, NN*3, cv, NN, S, NN, NN*NN);
    topk_block<<<BN, 256>>>(S, idx);
    make_wstack<<<(128*3+255)/256, 256>>>(w1, 64, 3, Wc);
    gemm128<<<dim3(1,64,1), 256>>>(3, X0, 3, 0, Wc, 3, 0, nullptr, 0, P, 128, 0);
    stats_edge<<<dim3(32,8), 256>>>(P, 128, P+64, 128, idx, 64, 6, part);
    reduce_stats<<<1, 64>>>(64, 163840.f, part, mean, istd);
    finalize_edge<<<dim3(32,8), 256>>>(P, 128, P+64, 128, idx, 64, 6, 0, g1, b1, mean, istd, XCAT);

    // ================= stage 2 : C=64 (x1 @ off 0) -> O=64, out [64,128) =======
    cvec_kernel<<<32, 256>>>(XCAT, 512, 64, cv);
    gemm128<<<dim3(8,8,8), 256>>>(64, XCAT, 512, NN*512, XCAT, 512, NN*512, cv, NN, S, NN, NN*NN);
    topk_block<<<BN, 256>>>(S, idx);
    make_wstack<<<(128*64+255)/256, 256>>>(w2, 64, 64, Wc);
    gemm128<<<dim3(1,64,1), 256>>>(64, XCAT, 512, 0, Wc, 64, 0, nullptr, 0, P, 128, 0);
    stats_edge<<<dim3(32,8), 256>>>(P, 128, P+64, 128, idx, 64, 6, part);
    reduce_stats<<<1, 64>>>(64, 163840.f, part, mean, istd);
    finalize_edge<<<dim3(32,8), 256>>>(P, 128, P+64, 128, idx, 64, 6, 64, g2, b2, mean, istd, XCAT);

    // ================= stage 3 : C=64 (x2 @ off 64) -> O=128, out [128,256) ====
    cvec_kernel<<<32, 256>>>(XCAT + 64, 512, 64, cv);
    gemm128<<<dim3(8,8,8), 256>>>(64, XCAT + 64, 512, NN*512, XCAT + 64, 512, NN*512, cv, NN, S, NN, NN*NN);
    topk_block<<<BN, 256>>>(S, idx);
    make_wstack<<<(256*64+255)/256, 256>>>(w3, 128, 64, Wc);
    gemm128<<<dim3(2,64,1), 256>>>(64, XCAT + 64, 512, 0, Wc, 64, 0, nullptr, 0, P, 256, 0);
    stats_edge<<<dim3(32,8), 256>>>(P, 256, P+128, 256, idx, 128, 7, part);
    reduce_stats<<<1, 128>>>(128, 163840.f, part, mean, istd);
    finalize_edge<<<dim3(32,8), 256>>>(P, 256, P+128, 256, idx, 128, 7, 128, g3, b3, mean, istd, XCAT);

    // ===== stage 4 : center x3 (C=128 @ off 128), source y -> O=256, out [256,512)
    gemm128<<<dim3(8,8,8), 256>>>(128, XCAT + 128, 512, NN*512, ynT, 128, NN*128,
                                  nullptr, 0, S, NN, NN*NN);
    topk_block<<<BN, 256>>>(S, idx);
    make_wc<<<(256*128+255)/256, 256>>>(w4, 256, 128, Wc);
    gemm128<<<dim3(2,64,1), 256>>>(128, yT, 128, 0, w4, 256, 0, nullptr, 0, P, 256, 0);
    gemm128<<<dim3(2,64,1), 256>>>(128, XCAT + 128, 512, 0, Wc, 128, 0, nullptr, 0, Q, 256, 0);
    stats_edge<<<dim3(32,8), 256>>>(P, 256, Q, 256, idx, 256, 8, part);
    reduce_stats<<<1, 256>>>(256, 163840.f, part, mean, istd);
    finalize_edge<<<dim3(32,8), 256>>>(P, 256, Q, 256, idx, 256, 8, 256, g4, b4, mean, istd, XCAT);

    // ================= stage 5 : 512 -> 512, BN over (B,N), write d_out ========
    gemm128<<<dim3(4,64,1), 256>>>(512, XCAT, 512, 0, w5, 512, 0, nullptr, 0, P, 512, 0);
    stats_plain<<<dim3(32,8), 512>>>(P, part);
    reduce_stats<<<1, 512>>>(512, 8192.f, part, mean, istd);
    finalize5<<<dim3(32,16,8), 256>>>(P, g5, b5, mean, istd, out);
}

// round 3
// speedup vs baseline: 4.6238x; 1.5920x over previous
#include <cuda_runtime.h>
#include <math.h>

#define BB 8
#define NN 1024
#define BN (BB*NN)
#define KNN 20
#define NEG 0.2f
#define EPS 1e-5f

// -------- scratch (device globals; no allocation allowed) --------
__device__ float g_X0[BN*3];          // x transposed (B,N,3)
__device__ float g_yT[BN*128];        // y transposed (B,M,128)
__device__ float g_ynT[BN*128];       // y normalized transposed
__device__ float g_XCAT[BN*512];      // concat of x1|x2|x3|x4 per point
__device__ float g_S[BB*NN*NN];       // score matrices (32MB)
__device__ float g_P[BN*512];         // PQ / stage5 pre-BN output
__device__ float g_Q[BN*256];         // stage4 Q
__device__ float g_Wc[512*128];       // stacked / combined weights
__device__ float g_cvec[BN];          // -0.5*|x_j|^2 column bias
__device__ int   g_idx[BN*KNN];       // knn indices
__device__ float g_part[2*256*512];   // BN partial sums
__device__ float g_mean[512];
__device__ float g_istd[512];

// -------- f32x2 packed helpers --------
__device__ __forceinline__ unsigned long long pack2(float x, float y) {
    unsigned long long r;
    asm("mov.b64 %0, {%1, %2};" : "=l"(r) : "f"(x), "f"(y));
    return r;
}
__device__ __forceinline__ void unpack2(unsigned long long v, float& x, float& y) {
    asm("mov.b64 {%0, %1}, %2;" : "=f"(x), "=f"(y) : "l"(v));
}
__device__ __forceinline__ void ffma2(unsigned long long& d,
                                      unsigned long long a, unsigned long long b) {
    asm("fma.rn.f32x2 %0, %1, %2, %0;" : "+l"(d) : "l"(a), "l"(b));
}

// -------- small prep kernels --------
__global__ void transpose_x(const float* __restrict__ x, float* __restrict__ X0) {
    int t = blockIdx.x*blockDim.x + threadIdx.x;
    if (t < BN) {
        int b = t >> 10, n = t & 1023;
        #pragma unroll
        for (int c = 0; c < 3; c++)
            X0[t*3 + c] = x[((size_t)b*3 + c)*NN + n];
    }
}

__global__ void prep_y(const float* __restrict__ y, float* __restrict__ yT,
                       float* __restrict__ ynT) {
    int m = blockIdx.x;            // global point 0..8191
    int b = m >> 10, mm = m & 1023;
    int c = threadIdx.x;           // 128
    float v = y[((size_t)b*128 + c)*NN + mm];
    __shared__ float red[128];
    red[c] = v*v;
    __syncthreads();
    for (int s = 64; s > 0; s >>= 1) {
        if (c < s) red[c] += red[c+s];
        __syncthreads();
    }
    float nrm = sqrtf(red[0]);
    float sc = 1.0f / fmaxf(nrm, 1e-12f);
    yT [(size_t)m*128 + c] = v;
    ynT[(size_t)m*128 + c] = v * sc;
}

__global__ void cvec_kernel(const float* __restrict__ A, int lda, int C,
                            float* __restrict__ cv) {
    int r = blockIdx.x*blockDim.x + threadIdx.x;
    if (r < BN) {
        float s = 0.f;
        for (int c = 0; c < C; c++) {
            float v = A[(size_t)r*lda + c];
            s += v*v;
        }
        cv[r] = -0.5f * s;
    }
}

// stacked weights: rows [0,O) = W1 (first C cols), rows [O,2O) = W2-W1
__global__ void make_wstack(const float* __restrict__ w, int O, int C,
                            float* __restrict__ out) {
    int e = blockIdx.x*blockDim.x + threadIdx.x;
    if (e < 2*O*C) {
        int r = e / C, c = e % C;
        float v;
        if (r < O) v = w[r*2*C + c];
        else { int o = r - O; v = w[o*2*C + C + c] - w[o*2*C + c]; }
        out[e] = v;
    }
}

__global__ void make_wc(const float* __restrict__ w, int O, int C,
                        float* __restrict__ Wc) {
    int e = blockIdx.x*blockDim.x + threadIdx.x;
    if (e < O*C) {
        int o = e / C, c = e % C;
        Wc[e] = w[o*2*C + C + c] - w[o*2*C + c];
    }
}

// -------- GEMM: C[r][c] = sum_k A[r][k]*B[c][k] (+ bias[c]) --------
// 128x128 tile, 256 threads, 8x8 microtile, f32x2 packed FMA, double-buffered.
__global__ void __launch_bounds__(256)
gemm128(int K,
        const float* __restrict__ A, int lda, int sA,
        const float* __restrict__ Bm, int ldb, int sB,
        const float* __restrict__ bias, int sBias,
        float* __restrict__ C, int ldc, int sC) {
    __shared__ __align__(16) float As[2][16][132];
    __shared__ __align__(16) float Bs[2][16][132];
    int z = blockIdx.z;
    A  += (size_t)z * sA;
    Bm += (size_t)z * sB;
    C  += (size_t)z * sC;
    const float* bi = bias ? bias + (size_t)z * sBias : nullptr;
    int row0 = blockIdx.y * 128, col0 = blockIdx.x * 128;
    int tid = threadIdx.x;
    int ty = tid >> 4, tx = tid & 15;

    unsigned long long acc[8][4];
    #pragma unroll
    for (int i = 0; i < 8; i++)
        #pragma unroll
        for (int j = 0; j < 4; j++) acc[i][j] = 0ULL;

    int nt = (K + 15) / 16;
    float ra[8], rb[8];

    // prologue load tile 0
    #pragma unroll
    for (int l = 0; l < 8; l++) {
        int e = tid + l*256;
        int kk = e & 15, r = e >> 4;
        ra[l] = (kk < K) ? A [(size_t)(row0 + r)*lda + kk] : 0.f;
        rb[l] = (kk < K) ? Bm[(size_t)(col0 + r)*ldb + kk] : 0.f;
    }
    #pragma unroll
    for (int l = 0; l < 8; l++) {
        int e = tid + l*256;
        int kk = e & 15, r = e >> 4;
        As[0][kk][r] = ra[l];
        Bs[0][kk][r] = rb[l];
    }
    __syncthreads();

    for (int t = 0; t < nt; t++) {
        int buf = t & 1;
        if (t + 1 < nt) {
            int k0 = (t + 1) * 16;
            #pragma unroll
            for (int l = 0; l < 8; l++) {
                int e = tid + l*256;
                int kk = e & 15, r = e >> 4;
                int gk = k0 + kk;
                ra[l] = (gk < K) ? A [(size_t)(row0 + r)*lda + gk] : 0.f;
                rb[l] = (gk < K) ? Bm[(size_t)(col0 + r)*ldb + gk] : 0.f;
            }
        }
        #pragma unroll
        for (int kk = 0; kk < 16; kk++) {
            float4 a0 = *(const float4*)&As[buf][kk][ty*4];
            float4 a1 = *(const float4*)&As[buf][kk][ty*4 + 64];
            ulonglong2 bq0 = *(const ulonglong2*)&Bs[buf][kk][tx*4];
            ulonglong2 bq1 = *(const ulonglong2*)&Bs[buf][kk][tx*4 + 64];
            unsigned long long bb[4] = {bq0.x, bq0.y, bq1.x, bq1.y};
            float av[8] = {a0.x, a0.y, a0.z, a0.w, a1.x, a1.y, a1.z, a1.w};
            #pragma unroll
            for (int i = 0; i < 8; i++) {
                unsigned long long ad = pack2(av[i], av[i]);
                #pragma unroll
                for (int j = 0; j < 4; j++) ffma2(acc[i][j], ad, bb[j]);
            }
        }
        if (t + 1 < nt) {
            int nb = (t + 1) & 1;
            #pragma unroll
            for (int l = 0; l < 8; l++) {
                int e = tid + l*256;
                int kk = e & 15, r = e >> 4;
                As[nb][kk][r] = ra[l];
                Bs[nb][kk][r] = rb[l];
            }
            __syncthreads();
        }
    }
    #pragma unroll
    for (int i = 0; i < 8; i++) {
        int r = row0 + ((i >> 2) << 6) + ty*4 + (i & 3);
        int c0 = col0 + tx*4;
        int c1 = col0 + 64 + tx*4;
        float4 o0, o1;
        unpack2(acc[i][0], o0.x, o0.y);
        unpack2(acc[i][1], o0.z, o0.w);
        unpack2(acc[i][2], o1.x, o1.y);
        unpack2(acc[i][3], o1.z, o1.w);
        if (bi) {
            o0.x += bi[c0];   o0.y += bi[c0+1]; o0.z += bi[c0+2]; o0.w += bi[c0+3];
            o1.x += bi[c1];   o1.y += bi[c1+1]; o1.z += bi[c1+2]; o1.w += bi[c1+3];
        }
        *(float4*)&C[(size_t)r*ldc + c0] = o0;
        *(float4*)&C[(size_t)r*ldc + c1] = o1;
    }
}

// -------- per-row top-K: one WARP per row, no block barriers --------
__global__ void __launch_bounds__(256)
topk_warp(const float* __restrict__ S, int* __restrict__ out) {
    int warp = threadIdx.x >> 5, lane = threadIdx.x & 31;
    int r = blockIdx.x * 8 + warp;
    const float* row = S + (size_t)r * NN;
    float v[32];
    #pragma unroll
    for (int j = 0; j < 32; j++) v[j] = row[j*32 + lane];

    for (int k = 0; k < KNN; k++) {
        // register tree argmax over the 32 local values (ties -> lower j)
        float tv16[16]; int tj16[16];
        #pragma unroll
        for (int j = 0; j < 16; j++) {
            bool t = v[2*j+1] > v[2*j];
            tv16[j] = t ? v[2*j+1] : v[2*j];
            tj16[j] = t ? 2*j+1 : 2*j;
        }
        float tv8[8]; int tj8[8];
        #pragma unroll
        for (int j = 0; j < 8; j++) {
            bool t = tv16[2*j+1] > tv16[2*j];
            tv8[j] = t ? tv16[2*j+1] : tv16[2*j];
            tj8[j] = t ? tj16[2*j+1] : tj16[2*j];
        }
        float tv4[4]; int tj4[4];
        #pragma unroll
        for (int j = 0; j < 4; j++) {
            bool t = tv8[2*j+1] > tv8[2*j];
            tv4[j] = t ? tv8[2*j+1] : tv8[2*j];
            tj4[j] = t ? tj8[2*j+1] : tj8[2*j];
        }
        float tv2[2]; int tj2[2];
        #pragma unroll
        for (int j = 0; j < 2; j++) {
            bool t = tv4[2*j+1] > tv4[2*j];
            tv2[j] = t ? tv4[2*j+1] : tv4[2*j];
            tj2[j] = t ? tj4[2*j+1] : tj4[2*j];
        }
        bool t0 = tv2[1] > tv2[0];
        float bv = t0 ? tv2[1] : tv2[0];
        int   bj = t0 ? tj2[1] : tj2[0];
        int   bg = bj*32 + lane;          // global column index

        // butterfly reduce across warp: max value, ties -> lower global index
        #pragma unroll
        for (int off = 16; off; off >>= 1) {
            float ov = __shfl_xor_sync(0xffffffffu, bv, off);
            int   og = __shfl_xor_sync(0xffffffffu, bg, off);
            if (ov > bv || (ov == bv && og < bg)) { bv = ov; bg = og; }
        }
        if (lane == 0) out[(size_t)r*KNN + k] = bg;

        // owner lane clears the chosen slot (predicated, keeps v[] in regs)
        int slot = bg >> 5;
        bool mine = (bg & 31) == lane;
        #pragma unroll
        for (int j = 0; j < 32; j++)
            if (mine && j == slot) v[j] = -1e30f;
    }
}

// -------- BN statistics over gathered edge features --------
__global__ void __launch_bounds__(256)
stats_edge(const float* __restrict__ P, int ldp,
           const float* __restrict__ Q, int ldq,
           const int* __restrict__ idx, int O, int oshift,
           float* __restrict__ part) {
    __shared__ int sIdx[32*KNN];
    __shared__ float red1[256], red2[256];
    int b = blockIdx.y, i0 = blockIdx.x * 32;
    for (int e = threadIdx.x; e < 32*KNN; e += 256)
        sIdx[e] = idx[(size_t)(b*NN + i0)*KNN + e];
    __syncthreads();
    int o  = threadIdx.x & (O-1);
    int pp = threadIdx.x >> oshift;
    int PP = 256 >> oshift;
    float s1 = 0.f, s2 = 0.f;
    for (int ii = pp; ii < 32; ii += PP) {
        int gi = b*NN + i0 + ii;
        float qv = Q[(size_t)gi*ldq + o];
        #pragma unroll 4
        for (int k = 0; k < KNN; k++) {
            int j = sIdx[ii*KNN + k];
            float pv = P[(size_t)(b*NN + j)*ldp + o];
            float vv = pv + qv;
            s1 += vv; s2 += vv*vv;
        }
    }
    red1[threadIdx.x] = s1; red2[threadIdx.x] = s2;
    __syncthreads();
    if (pp == 0) {
        for (int p = 1; p < PP; p++) { s1 += red1[o + p*O]; s2 += red2[o + p*O]; }
        int grp = blockIdx.y * gridDim.x + blockIdx.x;   // < 256
        part[(size_t)grp*O + o]         = s1;
        part[(size_t)(256 + grp)*O + o] = s2;
    }
}

__global__ void stats_plain(const float* __restrict__ P, float* __restrict__ part) {
    int b = blockIdx.y, i0 = blockIdx.x * 32;
    int o = threadIdx.x;  // 512
    float s1 = 0.f, s2 = 0.f;
    for (int ii = 0; ii < 32; ii++) {
        float v = P[(size_t)(b*NN + i0 + ii)*512 + o];
        s1 += v; s2 += v*v;
    }
    int grp = blockIdx.y * gridDim.x + blockIdx.x;
    part[(size_t)grp*512 + o]         = s1;
    part[(size_t)(256 + grp)*512 + o] = s2;
}

// warp-per-channel reduction over 256 groups. grid = O/8, block = 256.
__global__ void __launch_bounds__(256)
reduce_stats(int O, float cnt, const float* __restrict__ part,
             float* __restrict__ mean, float* __restrict__ istd) {
    int warp = threadIdx.x >> 5, lane = threadIdx.x & 31;
    int o = blockIdx.x*8 + warp;
    float s1 = 0.f, s2 = 0.f;
    #pragma unroll
    for (int g = lane; g < 256; g += 32) {
        s1 += part[(size_t)g*O + o];
        s2 += part[(size_t)(256 + g)*O + o];
    }
    #pragma unroll
    for (int off = 16; off; off >>= 1) {
        s1 += __shfl_down_sync(0xffffffffu, s1, off);
        s2 += __shfl_down_sync(0xffffffffu, s2, off);
    }
    if (lane == 0) {
        float m = s1 / cnt;
        float var = s2 / cnt - m*m;
        mean[o] = m;
        istd[o] = rsqrtf(var + EPS);
    }
}

// -------- fused normalize + lrelu + max-pool over K into XCAT slice --------
__global__ void __launch_bounds__(256)
finalize_edge(const float* __restrict__ P, int ldp,
              const float* __restrict__ Q, int ldq,
              const int* __restrict__ idx, int O, int oshift, int choff,
              const float* __restrict__ ga, const float* __restrict__ be,
              const float* __restrict__ mean, const float* __restrict__ istd,
              float* __restrict__ XCAT) {
    __shared__ int sIdx[32*KNN];
    int b = blockIdx.y, i0 = blockIdx.x * 32;
    for (int e = threadIdx.x; e < 32*KNN; e += 256)
        sIdx[e] = idx[(size_t)(b*NN + i0)*KNN + e];
    __syncthreads();
    int o  = threadIdx.x & (O-1);
    int pp = threadIdx.x >> oshift;
    int PP = 256 >> oshift;
    float m = mean[o], is = istd[o], g = ga[o], bb = be[o];
    for (int ii = pp; ii < 32; ii += PP) {
        int gi = b*NN + i0 + ii;
        float qv = Q[(size_t)gi*ldq + o];
        float mx = -1e30f;
        #pragma unroll 4
        for (int k = 0; k < KNN; k++) {
            int j = sIdx[ii*KNN + k];
            float v = P[(size_t)(b*NN + j)*ldp + o] + qv;
            float z = (v - m)*is*g + bb;
            z = (z >= 0.f) ? z : NEG*z;
            mx = fmaxf(mx, z);
        }
        XCAT[(size_t)gi*512 + choff + o] = mx;
    }
}

// -------- final BN+lrelu with transposed write to d_out (B,512,N) --------
__global__ void finalize5(const float* __restrict__ P,
                          const float* __restrict__ ga, const float* __restrict__ be,
                          const float* __restrict__ mean, const float* __restrict__ istd,
                          float* __restrict__ out) {
    __shared__ float tile[32][33];
    int b = blockIdx.z, o0 = blockIdx.y * 32, n0 = blockIdx.x * 32;
    int tid = threadIdx.x;
    #pragma unroll
    for (int l = 0; l < 4; l++) {
        int e = tid + l*256;
        int nn = e >> 5, oo = e & 31;
        int o = o0 + oo;
        float v = P[(size_t)(b*NN + n0 + nn)*512 + o];
        v = (v - mean[o]) * istd[o] * ga[o] + be[o];
        v = (v >= 0.f) ? v : NEG*v;
        tile[oo][nn] = v;
    }
    __syncthreads();
    #pragma unroll
    for (int l = 0; l < 4; l++) {
        int e = tid + l*256;
        int oo = e >> 5, nn = e & 31;
        out[(size_t)b*512*NN + (size_t)(o0 + oo)*NN + n0 + nn] = tile[oo][nn];
    }
}

extern "C" void kernel_launch(void* const* d_in, const int* in_sizes, int n_in,
                              void* d_out, int out_size) {
    const float* x  = (const float*)d_in[0];
    const float* y  = (const float*)d_in[1];
    const float* w1 = (const float*)d_in[2];
    const float* w2 = (const float*)d_in[3];
    const float* w3 = (const float*)d_in[4];
    const float* w4 = (const float*)d_in[5];
    const float* w5 = (const float*)d_in[6];
    const float* g1 = (const float*)d_in[7];  const float* b1 = (const float*)d_in[8];
    const float* g2 = (const float*)d_in[9];  const float* b2 = (const float*)d_in[10];
    const float* g3 = (const float*)d_in[11]; const float* b3 = (const float*)d_in[12];
    const float* g4 = (const float*)d_in[13]; const float* b4 = (const float*)d_in[14];
    const float* g5 = (const float*)d_in[15]; const float* b5 = (const float*)d_in[16];
    float* out = (float*)d_out;

    float *X0, *yT, *ynT, *XCAT, *S, *P, *Q, *Wc, *cv, *part, *mean, *istd;
    int* idx;
    cudaGetSymbolAddress((void**)&X0,  g_X0);
    cudaGetSymbolAddress((void**)&yT,  g_yT);
    cudaGetSymbolAddress((void**)&ynT, g_ynT);
    cudaGetSymbolAddress((void**)&XCAT,g_XCAT);
    cudaGetSymbolAddress((void**)&S,   g_S);
    cudaGetSymbolAddress((void**)&P,   g_P);
    cudaGetSymbolAddress((void**)&Q,   g_Q);
    cudaGetSymbolAddress((void**)&Wc,  g_Wc);
    cudaGetSymbolAddress((void**)&cv,  g_cvec);
    cudaGetSymbolAddress((void**)&idx, g_idx);
    cudaGetSymbolAddress((void**)&part,g_part);
    cudaGetSymbolAddress((void**)&mean,g_mean);
    cudaGetSymbolAddress((void**)&istd,g_istd);

    transpose_x<<<(BN+255)/256, 256>>>(x, X0);
    prep_y<<<BN, 128>>>(y, yT, ynT);

    // ================= stage 1 : C=3 -> O=64, out slice [0,64) =================
    cvec_kernel<<<32, 256>>>(X0, 3, 3, cv);
    gemm128<<<dim3(8,8,8), 256>>>(3, X0, 3, NN*3, X0, 3, NN*3, cv, NN, S, NN, NN*NN);
    topk_warp<<<BN/8, 256>>>(S, idx);
    make_wstack<<<(128*3+255)/256, 256>>>(w1, 64, 3, Wc);
    gemm128<<<dim3(1,64,1), 256>>>(3, X0, 3, 0, Wc, 3, 0, nullptr, 0, P, 128, 0);
    stats_edge<<<dim3(32,8), 256>>>(P, 128, P+64, 128, idx, 64, 6, part);
    reduce_stats<<<8, 256>>>(64, 163840.f, part, mean, istd);
    finalize_edge<<<dim3(32,8), 256>>>(P, 128, P+64, 128, idx, 64, 6, 0, g1, b1, mean, istd, XCAT);

    // ================= stage 2 : C=64 (x1 @ off 0) -> O=64, out [64,128) =======
    cvec_kernel<<<32, 256>>>(XCAT, 512, 64, cv);
    gemm128<<<dim3(8,8,8), 256>>>(64, XCAT, 512, NN*512, XCAT, 512, NN*512, cv, NN, S, NN, NN*NN);
    topk_warp<<<BN/8, 256>>>(S, idx);
    make_wstack<<<(128*64+255)/256, 256>>>(w2, 64, 64, Wc);
    gemm128<<<dim3(1,64,1), 256>>>(64, XCAT, 512, 0, Wc, 64, 0, nullptr, 0, P, 128, 0);
    stats_edge<<<dim3(32,8), 256>>>(P, 128, P+64, 128, idx, 64, 6, part);
    reduce_stats<<<8, 256>>>(64, 163840.f, part, mean, istd);
    finalize_edge<<<dim3(32,8), 256>>>(P, 128, P+64, 128, idx, 64, 6, 64, g2, b2, mean, istd, XCAT);

    // ================= stage 3 : C=64 (x2 @ off 64) -> O=128, out [128,256) ====
    cvec_kernel<<<32, 256>>>(XCAT + 64, 512, 64, cv);
    gemm128<<<dim3(8,8,8), 256>>>(64, XCAT + 64, 512, NN*512, XCAT + 64, 512, NN*512, cv, NN, S, NN, NN*NN);
    topk_warp<<<BN/8, 256>>>(S, idx);
    make_wstack<<<(256*64+255)/256, 256>>>(w3, 128, 64, Wc);
    gemm128<<<dim3(2,64,1), 256>>>(64, XCAT + 64, 512, 0, Wc, 64, 0, nullptr, 0, P, 256, 0);
    stats_edge<<<dim3(32,8), 256>>>(P, 256, P+128, 256, idx, 128, 7, part);
    reduce_stats<<<16, 256>>>(128, 163840.f, part, mean, istd);
    finalize_edge<<<dim3(32,8), 256>>>(P, 256, P+128, 256, idx, 128, 7, 128, g3, b3, mean, istd, XCAT);

    // ===== stage 4 : center x3 (C=128 @ off 128), source y -> O=256, out [256,512)
    gemm128<<<dim3(8,8,8), 256>>>(128, XCAT + 128, 512, NN*512, ynT, 128, NN*128,
                                  nullptr, 0, S, NN, NN*NN);
    topk_warp<<<BN/8, 256>>>(S, idx);
    make_wc<<<(256*128+255)/256, 256>>>(w4, 256, 128, Wc);
    gemm128<<<dim3(2,64,1), 256>>>(128, yT, 128, 0, w4, 256, 0, nullptr, 0, P, 256, 0);
    gemm128<<<dim3(2,64,1), 256>>>(128, XCAT + 128, 512, 0, Wc, 128, 0, nullptr, 0, Q, 256, 0);
    stats_edge<<<dim3(32,8), 256>>>(P, 256, Q, 256, idx, 256, 8, part);
    reduce_stats<<<32, 256>>>(256, 163840.f, part, mean, istd);
    finalize_edge<<<dim3(32,8), 256>>>(P, 256, Q, 256, idx, 256, 8, 256, g4, b4, mean, istd, XCAT);

    // ================= stage 5 : 512 -> 512, BN over (B,N), write d_out ========
    gemm128<<<dim3(4,64,1), 256>>>(512, XCAT, 512, 0, w5, 512, 0, nullptr, 0, P, 512, 0);
    stats_plain<<<dim3(32,8), 512>>>(P, part);
    reduce_stats<<<64, 256>>>(512, 8192.f, part, mean, istd);
    finalize5<<<dim3(32,16,8), 256>>>(P, g5, b5, mean, istd, out);
}

// round 4
// speedup vs baseline: 5.0240x; 1.0866x over previous
#include <cuda_runtime.h>
#include <math.h>

#define BB 8
#define NN 1024
#define BN (BB*NN)
#define KNN 20
#define NEG 0.2f
#define EPS 1e-5f

// -------- scratch (device globals; no allocation allowed) --------
__device__ float g_X0[BN*3];          // x transposed (B,N,3)
__device__ float g_yT[BN*128];        // y transposed (B,M,128)
__device__ float g_ynT[BN*128];       // y normalized transposed
__device__ float g_XCAT[BN*512];      // concat of x1|x2|x3|x4 per point
__device__ float g_S[BB*NN*NN];       // score matrices (32MB); reused as Mx/Mn
__device__ float g_P[BN*512];         // PQ / stage5 pre-BN output
__device__ float g_Q[BN*256];         // stage4 Q
__device__ float g_Wc[512*128];       // stacked / combined weights
__device__ float g_cvec[BN];          // -0.5*|x_j|^2 column bias
__device__ int   g_idx[BN*KNN];       // knn indices
__device__ float g_part[2*256*512];   // BN partial sums
__device__ float g_mean[512];
__device__ float g_istd[512];

// -------- f32x2 packed helpers --------
__device__ __forceinline__ unsigned long long pack2(float x, float y) {
    unsigned long long r;
    asm("mov.b64 %0, {%1, %2};" : "=l"(r) : "f"(x), "f"(y));
    return r;
}
__device__ __forceinline__ void unpack2(unsigned long long v, float& x, float& y) {
    asm("mov.b64 {%0, %1}, %2;" : "=f"(x), "=f"(y) : "l"(v));
}
__device__ __forceinline__ void ffma2(unsigned long long& d,
                                      unsigned long long a, unsigned long long b) {
    asm("fma.rn.f32x2 %0, %1, %2, %0;" : "+l"(d) : "l"(a), "l"(b));
}

// -------- small prep kernels --------
__global__ void transpose_x(const float* __restrict__ x, float* __restrict__ X0) {
    int t = blockIdx.x*blockDim.x + threadIdx.x;
    if (t < BN) {
        int b = t >> 10, n = t & 1023;
        #pragma unroll
        for (int c = 0; c < 3; c++)
            X0[t*3 + c] = x[((size_t)b*3 + c)*NN + n];
    }
}

__global__ void prep_y(const float* __restrict__ y, float* __restrict__ yT,
                       float* __restrict__ ynT) {
    int m = blockIdx.x;            // global point 0..8191
    int b = m >> 10, mm = m & 1023;
    int c = threadIdx.x;           // 128
    float v = y[((size_t)b*128 + c)*NN + mm];
    __shared__ float red[128];
    red[c] = v*v;
    __syncthreads();
    for (int s = 64; s > 0; s >>= 1) {
        if (c < s) red[c] += red[c+s];
        __syncthreads();
    }
    float nrm = sqrtf(red[0]);
    float sc = 1.0f / fmaxf(nrm, 1e-12f);
    yT [(size_t)m*128 + c] = v;
    ynT[(size_t)m*128 + c] = v * sc;
}

// warp-per-row |row|^2
__global__ void __launch_bounds__(256)
cvec_warp(const float* __restrict__ A, int lda, int C, float* __restrict__ cv) {
    int warp = threadIdx.x >> 5, lane = threadIdx.x & 31;
    int r = blockIdx.x*8 + warp;
    float s = 0.f;
    for (int c = lane; c < C; c += 32) {
        float v = A[(size_t)r*lda + c];
        s += v*v;
    }
    #pragma unroll
    for (int off = 16; off; off >>= 1)
        s += __shfl_down_sync(0xffffffffu, s, off);
    if (lane == 0) cv[r] = -0.5f * s;
}

// stacked weights: rows [0,O) = W1 (first C cols), rows [O,2O) = W2-W1
__global__ void make_wstack(const float* __restrict__ w, int O, int C,
                            float* __restrict__ out) {
    int e = blockIdx.x*blockDim.x + threadIdx.x;
    if (e < 2*O*C) {
        int r = e / C, c = e % C;
        float v;
        if (r < O) v = w[r*2*C + c];
        else { int o = r - O; v = w[o*2*C + C + c] - w[o*2*C + c]; }
        out[e] = v;
    }
}

__global__ void make_wc(const float* __restrict__ w, int O, int C,
                        float* __restrict__ Wc) {
    int e = blockIdx.x*blockDim.x + threadIdx.x;
    if (e < O*C) {
        int o = e / C, c = e % C;
        Wc[e] = w[o*2*C + C + c] - w[o*2*C + c];
    }
}

// -------- GEMM: C[r][c] = sum_k A[r][k]*B[c][k] (+ bias[c]) --------
// 128x128 tile, 256 threads, 8x8 microtile, f32x2 FMA, double-buffered.
// vec=1 requires K%16==0 and 16B-aligned rows on both A and B.
__global__ void __launch_bounds__(256)
gemm128(int K, int vec,
        const float* __restrict__ A, int lda, int sA,
        const float* __restrict__ Bm, int ldb, int sB,
        const float* __restrict__ bias, int sBias,
        float* __restrict__ C, int ldc, int sC) {
    __shared__ __align__(16) float As[2][16][132];
    __shared__ __align__(16) float Bs[2][16][132];
    int z = blockIdx.z;
    A  += (size_t)z * sA;
    Bm += (size_t)z * sB;
    C  += (size_t)z * sC;
    const float* bi = bias ? bias + (size_t)z * sBias : nullptr;
    int row0 = blockIdx.y * 128, col0 = blockIdx.x * 128;
    int tid = threadIdx.x;
    int ty = tid >> 4, tx = tid & 15;

    unsigned long long acc[8][4];
    #pragma unroll
    for (int i = 0; i < 8; i++)
        #pragma unroll
        for (int j = 0; j < 4; j++) acc[i][j] = 0ULL;

    int nt = (K + 15) / 16;
    float ra[8], rb[8];
    float4 ra4[2], rb4[2];
    int vr = tid >> 2, vk = (tid & 3) * 4;          // float4 mapping (l adds 64 rows)

    // prologue: load tile 0
    if (vec) {
        #pragma unroll
        for (int l = 0; l < 2; l++) {
            ra4[l] = *(const float4*)&A [(size_t)(row0 + vr + l*64)*lda + vk];
            rb4[l] = *(const float4*)&Bm[(size_t)(col0 + vr + l*64)*ldb + vk];
        }
        #pragma unroll
        for (int l = 0; l < 2; l++) {
            int r = vr + l*64;
            As[0][vk+0][r] = ra4[l].x; As[0][vk+1][r] = ra4[l].y;
            As[0][vk+2][r] = ra4[l].z; As[0][vk+3][r] = ra4[l].w;
            Bs[0][vk+0][r] = rb4[l].x; Bs[0][vk+1][r] = rb4[l].y;
            Bs[0][vk+2][r] = rb4[l].z; Bs[0][vk+3][r] = rb4[l].w;
        }
    } else {
        #pragma unroll
        for (int l = 0; l < 8; l++) {
            int e = tid + l*256;
            int kk = e & 15, r = e >> 4;
            ra[l] = (kk < K) ? A [(size_t)(row0 + r)*lda + kk] : 0.f;
            rb[l] = (kk < K) ? Bm[(size_t)(col0 + r)*ldb + kk] : 0.f;
        }
        #pragma unroll
        for (int l = 0; l < 8; l++) {
            int e = tid + l*256;
            int kk = e & 15, r = e >> 4;
            As[0][kk][r] = ra[l];
            Bs[0][kk][r] = rb[l];
        }
    }
    __syncthreads();

    for (int t = 0; t < nt; t++) {
        int buf = t & 1;
        if (t + 1 < nt) {
            int k0 = (t + 1) * 16;
            if (vec) {
                #pragma unroll
                for (int l = 0; l < 2; l++) {
                    ra4[l] = *(const float4*)&A [(size_t)(row0 + vr + l*64)*lda + k0 + vk];
                    rb4[l] = *(const float4*)&Bm[(size_t)(col0 + vr + l*64)*ldb + k0 + vk];
                }
            } else {
                #pragma unroll
                for (int l = 0; l < 8; l++) {
                    int e = tid + l*256;
                    int kk = e & 15, r = e >> 4;
                    int gk = k0 + kk;
                    ra[l] = (gk < K) ? A [(size_t)(row0 + r)*lda + gk] : 0.f;
                    rb[l] = (gk < K) ? Bm[(size_t)(col0 + r)*ldb + gk] : 0.f;
                }
            }
        }
        #pragma unroll
        for (int kk = 0; kk < 16; kk++) {
            float4 a0 = *(const float4*)&As[buf][kk][ty*4];
            float4 a1 = *(const float4*)&As[buf][kk][ty*4 + 64];
            ulonglong2 bq0 = *(const ulonglong2*)&Bs[buf][kk][tx*4];
            ulonglong2 bq1 = *(const ulonglong2*)&Bs[buf][kk][tx*4 + 64];
            unsigned long long bb[4] = {bq0.x, bq0.y, bq1.x, bq1.y};
            float av[8] = {a0.x, a0.y, a0.z, a0.w, a1.x, a1.y, a1.z, a1.w};
            #pragma unroll
            for (int i = 0; i < 8; i++) {
                unsigned long long ad = pack2(av[i], av[i]);
                #pragma unroll
                for (int j = 0; j < 4; j++) ffma2(acc[i][j], ad, bb[j]);
            }
        }
        if (t + 1 < nt) {
            int nb = (t + 1) & 1;
            if (vec) {
                #pragma unroll
                for (int l = 0; l < 2; l++) {
                    int r = vr + l*64;
                    As[nb][vk+0][r] = ra4[l].x; As[nb][vk+1][r] = ra4[l].y;
                    As[nb][vk+2][r] = ra4[l].z; As[nb][vk+3][r] = ra4[l].w;
                    Bs[nb][vk+0][r] = rb4[l].x; Bs[nb][vk+1][r] = rb4[l].y;
                    Bs[nb][vk+2][r] = rb4[l].z; Bs[nb][vk+3][r] = rb4[l].w;
                }
            } else {
                #pragma unroll
                for (int l = 0; l < 8; l++) {
                    int e = tid + l*256;
                    int kk = e & 15, r = e >> 4;
                    As[nb][kk][r] = ra[l];
                    Bs[nb][kk][r] = rb[l];
                }
            }
            __syncthreads();
        }
    }
    #pragma unroll
    for (int i = 0; i < 8; i++) {
        int r = row0 + ((i >> 2) << 6) + ty*4 + (i & 3);
        int c0 = col0 + tx*4;
        int c1 = col0 + 64 + tx*4;
        float4 o0, o1;
        unpack2(acc[i][0], o0.x, o0.y);
        unpack2(acc[i][1], o0.z, o0.w);
        unpack2(acc[i][2], o1.x, o1.y);
        unpack2(acc[i][3], o1.z, o1.w);
        if (bi) {
            o0.x += bi[c0];   o0.y += bi[c0+1]; o0.z += bi[c0+2]; o0.w += bi[c0+3];
            o1.x += bi[c1];   o1.y += bi[c1+1]; o1.z += bi[c1+2]; o1.w += bi[c1+3];
        }
        *(float4*)&C[(size_t)r*ldc + c0] = o0;
        *(float4*)&C[(size_t)r*ldc + c1] = o1;
    }
}

// -------- per-row top-K: one WARP per row, no block barriers --------
__global__ void __launch_bounds__(256)
topk_warp(const float* __restrict__ S, int* __restrict__ out) {
    int warp = threadIdx.x >> 5, lane = threadIdx.x & 31;
    int r = blockIdx.x * 8 + warp;
    const float* row = S + (size_t)r * NN;
    float v[32];
    #pragma unroll
    for (int j = 0; j < 32; j++) v[j] = row[j*32 + lane];

    for (int k = 0; k < KNN; k++) {
        float tv16[16]; int tj16[16];
        #pragma unroll
        for (int j = 0; j < 16; j++) {
            bool t = v[2*j+1] > v[2*j];
            tv16[j] = t ? v[2*j+1] : v[2*j];
            tj16[j] = t ? 2*j+1 : 2*j;
        }
        float tv8[8]; int tj8[8];
        #pragma unroll
        for (int j = 0; j < 8; j++) {
            bool t = tv16[2*j+1] > tv16[2*j];
            tv8[j] = t ? tv16[2*j+1] : tv16[2*j];
            tj8[j] = t ? tj16[2*j+1] : tj16[2*j];
        }
        float tv4[4]; int tj4[4];
        #pragma unroll
        for (int j = 0; j < 4; j++) {
            bool t = tv8[2*j+1] > tv8[2*j];
            tv4[j] = t ? tv8[2*j+1] : tv8[2*j];
            tj4[j] = t ? tj8[2*j+1] : tj8[2*j];
        }
        float tv2[2]; int tj2[2];
        #pragma unroll
        for (int j = 0; j < 2; j++) {
            bool t = tv4[2*j+1] > tv4[2*j];
            tv2[j] = t ? tv4[2*j+1] : tv4[2*j];
            tj2[j] = t ? tj4[2*j+1] : tj4[2*j];
        }
        bool t0 = tv2[1] > tv2[0];
        float bv = t0 ? tv2[1] : tv2[0];
        int   bj = t0 ? tj2[1] : tj2[0];
        int   bg = bj*32 + lane;

        #pragma unroll
        for (int off = 16; off; off >>= 1) {
            float ov = __shfl_xor_sync(0xffffffffu, bv, off);
            int   og = __shfl_xor_sync(0xffffffffu, bg, off);
            if (ov > bv || (ov == bv && og < bg)) { bv = ov; bg = og; }
        }
        if (lane == 0) out[(size_t)r*KNN + k] = bg;

        int slot = bg >> 5;
        bool mine = (bg & 31) == lane;
        #pragma unroll
        for (int j = 0; j < 32; j++)
            if (mine && j == slot) v[j] = -1e30f;
    }
}

// -------- single gather pass: BN stats + per-(point,channel) max/min --------
__global__ void __launch_bounds__(256)
stats_mm_edge(const float* __restrict__ P, int ldp,
              const float* __restrict__ Q, int ldq,
              const int* __restrict__ idx, int O, int oshift,
              float* __restrict__ part,
              float* __restrict__ Mx, float* __restrict__ Mn) {
    __shared__ int sIdx[32*KNN];
    __shared__ float red1[256], red2[256];
    int b = blockIdx.y, i0 = blockIdx.x * 32;
    for (int e = threadIdx.x; e < 32*KNN; e += 256)
        sIdx[e] = idx[(size_t)(b*NN + i0)*KNN + e];
    __syncthreads();
    int o  = threadIdx.x & (O-1);
    int pp = threadIdx.x >> oshift;
    int PP = 256 >> oshift;
    float s1 = 0.f, s2 = 0.f;
    for (int ii = pp; ii < 32; ii += PP) {
        int gi = b*NN + i0 + ii;
        float qv = Q[(size_t)gi*ldq + o];
        float mx = -1e30f, mn = 1e30f;
        #pragma unroll 4
        for (int k = 0; k < KNN; k++) {
            int j = sIdx[ii*KNN + k];
            float v = P[(size_t)(b*NN + j)*ldp + o] + qv;
            s1 += v; s2 += v*v;
            mx = fmaxf(mx, v); mn = fminf(mn, v);
        }
        Mx[(size_t)gi*O + o] = mx;
        Mn[(size_t)gi*O + o] = mn;
    }
    red1[threadIdx.x] = s1; red2[threadIdx.x] = s2;
    __syncthreads();
    if (pp == 0) {
        for (int p = 1; p < PP; p++) { s1 += red1[o + p*O]; s2 += red2[o + p*O]; }
        int grp = blockIdx.y * gridDim.x + blockIdx.x;   // < 256
        part[(size_t)grp*O + o]         = s1;
        part[(size_t)(256 + grp)*O + o] = s2;
    }
}

__global__ void stats_plain(const float* __restrict__ P, float* __restrict__ part) {
    int b = blockIdx.y, i0 = blockIdx.x * 32;
    int o = threadIdx.x;  // 512
    float s1 = 0.f, s2 = 0.f;
    for (int ii = 0; ii < 32; ii++) {
        float v = P[(size_t)(b*NN + i0 + ii)*512 + o];
        s1 += v; s2 += v*v;
    }
    int grp = blockIdx.y * gridDim.x + blockIdx.x;
    part[(size_t)grp*512 + o]         = s1;
    part[(size_t)(256 + grp)*512 + o] = s2;
}

// warp-per-channel reduction over 256 groups. grid = O/8, block = 256.
__global__ void __launch_bounds__(256)
reduce_stats(int O, float cnt, const float* __restrict__ part,
             float* __restrict__ mean, float* __restrict__ istd) {
    int warp = threadIdx.x >> 5, lane = threadIdx.x & 31;
    int o = blockIdx.x*8 + warp;
    float s1 = 0.f, s2 = 0.f;
    #pragma unroll
    for (int g = lane; g < 256; g += 32) {
        s1 += part[(size_t)g*O + o];
        s2 += part[(size_t)(256 + g)*O + o];
    }
    #pragma unroll
    for (int off = 16; off; off >>= 1) {
        s1 += __shfl_down_sync(0xffffffffu, s1, off);
        s2 += __shfl_down_sync(0xffffffffu, s2, off);
    }
    if (lane == 0) {
        float m = s1 / cnt;
        float var = s2 / cnt - m*m;
        mean[o] = m;
        istd[o] = rsqrtf(var + EPS);
    }
}

// -------- elementwise finalize from max/min (monotone BN+lrelu) --------
__global__ void __launch_bounds__(256)
finalize_mm(const float* __restrict__ Mx, const float* __restrict__ Mn,
            int O, int oshift, int choff,
            const float* __restrict__ ga, const float* __restrict__ be,
            const float* __restrict__ mean, const float* __restrict__ istd,
            float* __restrict__ XCAT) {
    int base = blockIdx.x * 32 * O;
    for (int e = threadIdx.x; e < 32*O; e += 256) {
        int t = base + e;
        int o = t & (O-1);
        int gi = t >> oshift;
        float scale = istd[o] * ga[o];
        float v = (scale >= 0.f) ? Mx[t] : Mn[t];
        float z = (v - mean[o]) * scale + be[o];
        z = (z >= 0.f) ? z : NEG*z;
        XCAT[(size_t)gi*512 + choff + o] = z;
    }
}

// -------- final BN+lrelu with transposed write to d_out (B,512,N) --------
__global__ void finalize5(const float* __restrict__ P,
                          const float* __restrict__ ga, const float* __restrict__ be,
                          const float* __restrict__ mean, const float* __restrict__ istd,
                          float* __restrict__ out) {
    __shared__ float tile[32][33];
    int b = blockIdx.z, o0 = blockIdx.y * 32, n0 = blockIdx.x * 32;
    int tid = threadIdx.x;
    #pragma unroll
    for (int l = 0; l < 4; l++) {
        int e = tid + l*256;
        int nn = e >> 5, oo = e & 31;
        int o = o0 + oo;
        float v = P[(size_t)(b*NN + n0 + nn)*512 + o];
        v = (v - mean[o]) * istd[o] * ga[o] + be[o];
        v = (v >= 0.f) ? v : NEG*v;
        tile[oo][nn] = v;
    }
    __syncthreads();
    #pragma unroll
    for (int l = 0; l < 4; l++) {
        int e = tid + l*256;
        int oo = e >> 5, nn = e & 31;
        out[(size_t)b*512*NN + (size_t)(o0 + oo)*NN + n0 + nn] = tile[oo][nn];
    }
}

extern "C" void kernel_launch(void* const* d_in, const int* in_sizes, int n_in,
                              void* d_out, int out_size) {
    const float* x  = (const float*)d_in[0];
    const float* y  = (const float*)d_in[1];
    const float* w1 = (const float*)d_in[2];
    const float* w2 = (const float*)d_in[3];
    const float* w3 = (const float*)d_in[4];
    const float* w4 = (const float*)d_in[5];
    const float* w5 = (const float*)d_in[6];
    const float* g1 = (const float*)d_in[7];  const float* b1 = (const float*)d_in[8];
    const float* g2 = (const float*)d_in[9];  const float* b2 = (const float*)d_in[10];
    const float* g3 = (const float*)d_in[11]; const float* b3 = (const float*)d_in[12];
    const float* g4 = (const float*)d_in[13]; const float* b4 = (const float*)d_in[14];
    const float* g5 = (const float*)d_in[15]; const float* b5 = (const float*)d_in[16];
    float* out = (float*)d_out;

    float *X0, *yT, *ynT, *XCAT, *S, *P, *Q, *Wc, *cv, *part, *mean, *istd;
    int* idx;
    cudaGetSymbolAddress((void**)&X0,  g_X0);
    cudaGetSymbolAddress((void**)&yT,  g_yT);
    cudaGetSymbolAddress((void**)&ynT, g_ynT);
    cudaGetSymbolAddress((void**)&XCAT,g_XCAT);
    cudaGetSymbolAddress((void**)&S,   g_S);
    cudaGetSymbolAddress((void**)&P,   g_P);
    cudaGetSymbolAddress((void**)&Q,   g_Q);
    cudaGetSymbolAddress((void**)&Wc,  g_Wc);
    cudaGetSymbolAddress((void**)&cv,  g_cvec);
    cudaGetSymbolAddress((void**)&idx, g_idx);
    cudaGetSymbolAddress((void**)&part,g_part);
    cudaGetSymbolAddress((void**)&mean,g_mean);
    cudaGetSymbolAddress((void**)&istd,g_istd);

    float* Mx = S;                 // S is free after topk
    float* Mn = S + (size_t)BN*256;

    transpose_x<<<(BN+255)/256, 256>>>(x, X0);
    prep_y<<<BN, 128>>>(y, yT, ynT);

    // ================= stage 1 : C=3 -> O=64, out slice [0,64) =================
    cvec_warp<<<BN/8, 256>>>(X0, 3, 3, cv);
    gemm128<<<dim3(8,8,8), 256>>>(3, 0, X0, 3, NN*3, X0, 3, NN*3, cv, NN, S, NN, NN*NN);
    topk_warp<<<BN/8, 256>>>(S, idx);
    make_wstack<<<(128*3+255)/256, 256>>>(w1, 64, 3, Wc);
    gemm128<<<dim3(1,64,1), 256>>>(3, 0, X0, 3, 0, Wc, 3, 0, nullptr, 0, P, 128, 0);
    stats_mm_edge<<<dim3(32,8), 256>>>(P, 128, P+64, 128, idx, 64, 6, part, Mx, Mn);
    reduce_stats<<<8, 256>>>(64, 163840.f, part, mean, istd);
    finalize_mm<<<BN/32, 256>>>(Mx, Mn, 64, 6, 0, g1, b1, mean, istd, XCAT);

    // ================= stage 2 : C=64 (x1 @ off 0) -> O=64, out [64,128) =======
    cvec_warp<<<BN/8, 256>>>(XCAT, 512, 64, cv);
    gemm128<<<dim3(8,8,8), 256>>>(64, 1, XCAT, 512, NN*512, XCAT, 512, NN*512, cv, NN, S, NN, NN*NN);
    topk_warp<<<BN/8, 256>>>(S, idx);
    make_wstack<<<(128*64+255)/256, 256>>>(w2, 64, 64, Wc);
    gemm128<<<dim3(1,64,1), 256>>>(64, 1, XCAT, 512, 0, Wc, 64, 0, nullptr, 0, P, 128, 0);
    stats_mm_edge<<<dim3(32,8), 256>>>(P, 128, P+64, 128, idx, 64, 6, part, Mx, Mn);
    reduce_stats<<<8, 256>>>(64, 163840.f, part, mean, istd);
    finalize_mm<<<BN/32, 256>>>(Mx, Mn, 64, 6, 64, g2, b2, mean, istd, XCAT);

    // ================= stage 3 : C=64 (x2 @ off 64) -> O=128, out [128,256) ====
    cvec_warp<<<BN/8, 256>>>(XCAT + 64, 512, 64, cv);
    gemm128<<<dim3(8,8,8), 256>>>(64, 1, XCAT + 64, 512, NN*512, XCAT + 64, 512, NN*512, cv, NN, S, NN, NN*NN);
    topk_warp<<<BN/8, 256>>>(S, idx);
    make_wstack<<<(256*64+255)/256, 256>>>(w3, 128, 64, Wc);
    gemm128<<<dim3(2,64,1), 256>>>(64, 1, XCAT + 64, 512, 0, Wc, 64, 0, nullptr, 0, P, 256, 0);
    stats_mm_edge<<<dim3(32,8), 256>>>(P, 256, P+128, 256, idx, 128, 7, part, Mx, Mn);
    reduce_stats<<<16, 256>>>(128, 163840.f, part, mean, istd);
    finalize_mm<<<BN/32, 256>>>(Mx, Mn, 128, 7, 128, g3, b3, mean, istd, XCAT);

    // ===== stage 4 : center x3 (C=128 @ off 128), source y -> O=256, out [256,512)
    gemm128<<<dim3(8,8,8), 256>>>(128, 1, XCAT + 128, 512, NN*512, ynT, 128, NN*128,
                                  nullptr, 0, S, NN, NN*NN);
    topk_warp<<<BN/8, 256>>>(S, idx);
    make_wc<<<(256*128+255)/256, 256>>>(w4, 256, 128, Wc);
    gemm128<<<dim3(2,64,1), 256>>>(128, 1, yT, 128, 0, w4, 256, 0, nullptr, 0, P, 256, 0);
    gemm128<<<dim3(2,64,1), 256>>>(128, 1, XCAT + 128, 512, 0, Wc, 128, 0, nullptr, 0, Q, 256, 0);
    stats_mm_edge<<<dim3(32,8), 256>>>(P, 256, Q, 256, idx, 256, 8, part, Mx, Mn);
    reduce_stats<<<32, 256>>>(256, 163840.f, part, mean, istd);
    finalize_mm<<<BN/32, 256>>>(Mx, Mn, 256, 8, 256, g4, b4, mean, istd, XCAT);

    // ================= stage 5 : 512 -> 512, BN over (B,N), write d_out ========
    gemm128<<<dim3(4,64,1), 256>>>(512, 1, XCAT, 512, 0, w5, 512, 0, nullptr, 0, P, 512, 0);
    stats_plain<<<dim3(32,8), 512>>>(P, part);
    reduce_stats<<<64, 256>>>(512, 8192.f, part, mean, istd);
    finalize5<<<dim3(32,16,8), 256>>>(P, g5, b5, mean, istd, out);
}

// round 5
// speedup vs baseline: 5.2415x; 1.0433x over previous
#include <cuda_runtime.h>
#include <math.h>

#define BB 8
#define NN 1024
#define BN (BB*NN)
#define KNN 20
#define NEG 0.2f
#define EPS 1e-5f

// -------- scratch (device globals; no allocation allowed) --------
__device__ float g_X0[BN*3];          // x transposed (B,N,3)
__device__ float g_yT[BN*128];        // y transposed (B,M,128)
__device__ float g_ynT[BN*128];       // y normalized transposed
__device__ float g_XCAT[BN*512];      // concat of x1|x2|x3|x4 per point
__device__ float g_S[BB*NN*NN];       // score matrices (32MB); reused as Mx/Mn
__device__ float g_P[BN*512];         // PQ / stage5 pre-BN output
__device__ float g_Q[BN*256];         // stage4 Q
__device__ float g_Wc[512*128];       // stacked / combined weights
__device__ float g_cvec[BN];          // -0.5*|x_j|^2 column bias
__device__ int   g_idx[BN*KNN];       // knn indices
__device__ float g_part[2*256*512];   // BN partial sums
__device__ float g_mean[512];
__device__ float g_istd[512];

// -------- f32x2 packed helpers --------
__device__ __forceinline__ unsigned long long pack2(float x, float y) {
    unsigned long long r;
    asm("mov.b64 %0, {%1, %2};" : "=l"(r) : "f"(x), "f"(y));
    return r;
}
__device__ __forceinline__ void unpack2(unsigned long long v, float& x, float& y) {
    asm("mov.b64 {%0, %1}, %2;" : "=f"(x), "=f"(y) : "l"(v));
}
__device__ __forceinline__ void ffma2(unsigned long long& d,
                                      unsigned long long a, unsigned long long b) {
    asm("fma.rn.f32x2 %0, %1, %2, %0;" : "+l"(d) : "l"(a), "l"(b));
}

// -------- small prep kernels --------
__global__ void transpose_x(const float* __restrict__ x, float* __restrict__ X0) {
    int t = blockIdx.x*blockDim.x + threadIdx.x;
    if (t < BN) {
        int b = t >> 10, n = t & 1023;
        #pragma unroll
        for (int c = 0; c < 3; c++)
            X0[t*3 + c] = x[((size_t)b*3 + c)*NN + n];
    }
}

__global__ void prep_y(const float* __restrict__ y, float* __restrict__ yT,
                       float* __restrict__ ynT) {
    int m = blockIdx.x;            // global point 0..8191
    int b = m >> 10, mm = m & 1023;
    int c = threadIdx.x;           // 128
    float v = y[((size_t)b*128 + c)*NN + mm];
    __shared__ float red[128];
    red[c] = v*v;
    __syncthreads();
    for (int s = 64; s > 0; s >>= 1) {
        if (c < s) red[c] += red[c+s];
        __syncthreads();
    }
    float nrm = sqrtf(red[0]);
    float sc = 1.0f / fmaxf(nrm, 1e-12f);
    yT [(size_t)m*128 + c] = v;
    ynT[(size_t)m*128 + c] = v * sc;
}

// warp-per-row |row|^2
__global__ void __launch_bounds__(256)
cvec_warp(const float* __restrict__ A, int lda, int C, float* __restrict__ cv) {
    int warp = threadIdx.x >> 5, lane = threadIdx.x & 31;
    int r = blockIdx.x*8 + warp;
    float s = 0.f;
    for (int c = lane; c < C; c += 32) {
        float v = A[(size_t)r*lda + c];
        s += v*v;
    }
    #pragma unroll
    for (int off = 16; off; off >>= 1)
        s += __shfl_down_sync(0xffffffffu, s, off);
    if (lane == 0) cv[r] = -0.5f * s;
}

// stacked weights: rows [0,O) = W1 (first C cols), rows [O,2O) = W2-W1
__global__ void make_wstack(const float* __restrict__ w, int O, int C,
                            float* __restrict__ out) {
    int e = blockIdx.x*blockDim.x + threadIdx.x;
    if (e < 2*O*C) {
        int r = e / C, c = e % C;
        float v;
        if (r < O) v = w[r*2*C + c];
        else { int o = r - O; v = w[o*2*C + C + c] - w[o*2*C + c]; }
        out[e] = v;
    }
}

__global__ void make_wc(const float* __restrict__ w, int O, int C,
                        float* __restrict__ Wc) {
    int e = blockIdx.x*blockDim.x + threadIdx.x;
    if (e < O*C) {
        int o = e / C, c = e % C;
        Wc[e] = w[o*2*C + C + c] - w[o*2*C + c];
    }
}

// -------- GEMM: C[r][c] = sum_k A[r][k]*B[c][k] (+ bias[c]) --------
// 128x128 tile, 256 threads, 8x8 microtile, f32x2 FMA, double-buffered.
// minBlocks=2 caps regs at 128 -> 2 blocks/SM (16 warps).
__global__ void __launch_bounds__(256, 2)
gemm128(int K, int vec,
        const float* __restrict__ A, int lda, int sA,
        const float* __restrict__ Bm, int ldb, int sB,
        const float* __restrict__ bias, int sBias,
        float* __restrict__ C, int ldc, int sC) {
    __shared__ __align__(16) float As[2][16][132];
    __shared__ __align__(16) float Bs[2][16][132];
    int z = blockIdx.z;
    A  += (size_t)z * sA;
    Bm += (size_t)z * sB;
    C  += (size_t)z * sC;
    const float* bi = bias ? bias + (size_t)z * sBias : nullptr;
    int row0 = blockIdx.y * 128, col0 = blockIdx.x * 128;
    int tid = threadIdx.x;
    int ty = tid >> 4, tx = tid & 15;

    unsigned long long acc[8][4];
    #pragma unroll
    for (int i = 0; i < 8; i++)
        #pragma unroll
        for (int j = 0; j < 4; j++) acc[i][j] = 0ULL;

    int nt = (K + 15) / 16;
    float ra[8], rb[8];
    float4 ra4[2], rb4[2];
    int vr = tid >> 2, vk = (tid & 3) * 4;          // float4 mapping (l adds 64 rows)

    // prologue: load tile 0
    if (vec) {
        #pragma unroll
        for (int l = 0; l < 2; l++) {
            ra4[l] = *(const float4*)&A [(size_t)(row0 + vr + l*64)*lda + vk];
            rb4[l] = *(const float4*)&Bm[(size_t)(col0 + vr + l*64)*ldb + vk];
        }
        #pragma unroll
        for (int l = 0; l < 2; l++) {
            int r = vr + l*64;
            As[0][vk+0][r] = ra4[l].x; As[0][vk+1][r] = ra4[l].y;
            As[0][vk+2][r] = ra4[l].z; As[0][vk+3][r] = ra4[l].w;
            Bs[0][vk+0][r] = rb4[l].x; Bs[0][vk+1][r] = rb4[l].y;
            Bs[0][vk+2][r] = rb4[l].z; Bs[0][vk+3][r] = rb4[l].w;
        }
    } else {
        #pragma unroll
        for (int l = 0; l < 8; l++) {
            int e = tid + l*256;
            int kk = e & 15, r = e >> 4;
            ra[l] = (kk < K) ? A [(size_t)(row0 + r)*lda + kk] : 0.f;
            rb[l] = (kk < K) ? Bm[(size_t)(col0 + r)*ldb + kk] : 0.f;
        }
        #pragma unroll
        for (int l = 0; l < 8; l++) {
            int e = tid + l*256;
            int kk = e & 15, r = e >> 4;
            As[0][kk][r] = ra[l];
            Bs[0][kk][r] = rb[l];
        }
    }
    __syncthreads();

    for (int t = 0; t < nt; t++) {
        int buf = t & 1;
        if (t + 1 < nt) {
            int k0 = (t + 1) * 16;
            if (vec) {
                #pragma unroll
                for (int l = 0; l < 2; l++) {
                    ra4[l] = *(const float4*)&A [(size_t)(row0 + vr + l*64)*lda + k0 + vk];
                    rb4[l] = *(const float4*)&Bm[(size_t)(col0 + vr + l*64)*ldb + k0 + vk];
                }
            } else {
                #pragma unroll
                for (int l = 0; l < 8; l++) {
                    int e = tid + l*256;
                    int kk = e & 15, r = e >> 4;
                    int gk = k0 + kk;
                    ra[l] = (gk < K) ? A [(size_t)(row0 + r)*lda + gk] : 0.f;
                    rb[l] = (gk < K) ? Bm[(size_t)(col0 + r)*ldb + gk] : 0.f;
                }
            }
        }
        #pragma unroll
        for (int kk = 0; kk < 16; kk++) {
            float4 a0 = *(const float4*)&As[buf][kk][ty*4];
            float4 a1 = *(const float4*)&As[buf][kk][ty*4 + 64];
            ulonglong2 bq0 = *(const ulonglong2*)&Bs[buf][kk][tx*4];
            ulonglong2 bq1 = *(const ulonglong2*)&Bs[buf][kk][tx*4 + 64];
            unsigned long long bb[4] = {bq0.x, bq0.y, bq1.x, bq1.y};
            float av[8] = {a0.x, a0.y, a0.z, a0.w, a1.x, a1.y, a1.z, a1.w};
            #pragma unroll
            for (int i = 0; i < 8; i++) {
                unsigned long long ad = pack2(av[i], av[i]);
                #pragma unroll
                for (int j = 0; j < 4; j++) ffma2(acc[i][j], ad, bb[j]);
            }
        }
        if (t + 1 < nt) {
            int nb = (t + 1) & 1;
            if (vec) {
                #pragma unroll
                for (int l = 0; l < 2; l++) {
                    int r = vr + l*64;
                    As[nb][vk+0][r] = ra4[l].x; As[nb][vk+1][r] = ra4[l].y;
                    As[nb][vk+2][r] = ra4[l].z; As[nb][vk+3][r] = ra4[l].w;
                    Bs[nb][vk+0][r] = rb4[l].x; Bs[nb][vk+1][r] = rb4[l].y;
                    Bs[nb][vk+2][r] = rb4[l].z; Bs[nb][vk+3][r] = rb4[l].w;
                }
            } else {
                #pragma unroll
                for (int l = 0; l < 8; l++) {
                    int e = tid + l*256;
                    int kk = e & 15, r = e >> 4;
                    As[nb][kk][r] = ra[l];
                    Bs[nb][kk][r] = rb[l];
                }
            }
            __syncthreads();
        }
    }
    #pragma unroll
    for (int i = 0; i < 8; i++) {
        int r = row0 + ((i >> 2) << 6) + ty*4 + (i & 3);
        int c0 = col0 + tx*4;
        int c1 = col0 + 64 + tx*4;
        float4 o0, o1;
        unpack2(acc[i][0], o0.x, o0.y);
        unpack2(acc[i][1], o0.z, o0.w);
        unpack2(acc[i][2], o1.x, o1.y);
        unpack2(acc[i][3], o1.z, o1.w);
        if (bi) {
            o0.x += bi[c0];   o0.y += bi[c0+1]; o0.z += bi[c0+2]; o0.w += bi[c0+3];
            o1.x += bi[c1];   o1.y += bi[c1+1]; o1.z += bi[c1+2]; o1.w += bi[c1+3];
        }
        *(float4*)&C[(size_t)r*ldc + c0] = o0;
        *(float4*)&C[(size_t)r*ldc + c1] = o1;
    }
}

// -------- warp top-K over 32 register values per lane (column = j*32+lane) --------
__device__ __forceinline__ void warp_topk_regs(float (&v)[32], int r, int lane,
                                               int* __restrict__ out) {
    for (int k = 0; k < KNN; k++) {
        float tv16[16]; int tj16[16];
        #pragma unroll
        for (int j = 0; j < 16; j++) {
            bool t = v[2*j+1] > v[2*j];
            tv16[j] = t ? v[2*j+1] : v[2*j];
            tj16[j] = t ? 2*j+1 : 2*j;
        }
        float tv8[8]; int tj8[8];
        #pragma unroll
        for (int j = 0; j < 8; j++) {
            bool t = tv16[2*j+1] > tv16[2*j];
            tv8[j] = t ? tv16[2*j+1] : tv16[2*j];
            tj8[j] = t ? tj16[2*j+1] : tj16[2*j];
        }
        float tv4[4]; int tj4[4];
        #pragma unroll
        for (int j = 0; j < 4; j++) {
            bool t = tv8[2*j+1] > tv8[2*j];
            tv4[j] = t ? tv8[2*j+1] : tv8[2*j];
            tj4[j] = t ? tj8[2*j+1] : tj8[2*j];
        }
        float tv2[2]; int tj2[2];
        #pragma unroll
        for (int j = 0; j < 2; j++) {
            bool t = tv4[2*j+1] > tv4[2*j];
            tv2[j] = t ? tv4[2*j+1] : tv4[2*j];
            tj2[j] = t ? tj4[2*j+1] : tj4[2*j];
        }
        bool t0 = tv2[1] > tv2[0];
        float bv = t0 ? tv2[1] : tv2[0];
        int   bj = t0 ? tj2[1] : tj2[0];
        int   bg = bj*32 + lane;

        #pragma unroll
        for (int off = 16; off; off >>= 1) {
            float ov = __shfl_xor_sync(0xffffffffu, bv, off);
            int   og = __shfl_xor_sync(0xffffffffu, bg, off);
            if (ov > bv || (ov == bv && og < bg)) { bv = ov; bg = og; }
        }
        if (lane == 0) out[(size_t)r*KNN + k] = bg;

        int slot = bg >> 5;
        bool mine = (bg & 31) == lane;
        #pragma unroll
        for (int j = 0; j < 32; j++)
            if (mine && j == slot) v[j] = -1e30f;
    }
}

// -------- per-row top-K from a precomputed score matrix --------
__global__ void __launch_bounds__(256)
topk_warp(const float* __restrict__ S, int* __restrict__ out) {
    int warp = threadIdx.x >> 5, lane = threadIdx.x & 31;
    int r = blockIdx.x * 8 + warp;
    const float* row = S + (size_t)r * NN;
    float v[32];
    #pragma unroll
    for (int j = 0; j < 32; j++) v[j] = row[j*32 + lane];
    warp_topk_regs(v, r, lane, out);
}

// -------- stage 1 fused: compute xyz scores in regs + top-K (no S matrix) ----
__global__ void __launch_bounds__(256)
score1_topk(const float* __restrict__ X0, int* __restrict__ out) {
    int warp = threadIdx.x >> 5, lane = threadIdx.x & 31;
    int r = blockIdx.x * 8 + warp;          // global row (point i)
    int b = r >> 10;
    const float* Xb = X0 + (size_t)b * NN * 3;
    float cx = X0[(size_t)r*3+0], cy = X0[(size_t)r*3+1], cz = X0[(size_t)r*3+2];
    float v[32];
    #pragma unroll
    for (int j = 0; j < 32; j++) {
        int col = j*32 + lane;
        float xj = Xb[(size_t)col*3+0], yj = Xb[(size_t)col*3+1], zj = Xb[(size_t)col*3+2];
        float half = -0.5f * (xj*xj + yj*yj + zj*zj);
        v[j] = fmaf(cx, xj, fmaf(cy, yj, fmaf(cz, zj, half)));
    }
    warp_topk_regs(v, r, lane, out);
}

// -------- single gather pass: BN stats + per-(point,channel) max/min --------
__global__ void __launch_bounds__(256)
stats_mm_edge(const float* __restrict__ P, int ldp,
              const float* __restrict__ Q, int ldq,
              const int* __restrict__ idx, int O, int oshift,
              float* __restrict__ part,
              float* __restrict__ Mx, float* __restrict__ Mn) {
    __shared__ int sIdx[32*KNN];
    __shared__ float red1[256], red2[256];
    int b = blockIdx.y, i0 = blockIdx.x * 32;
    for (int e = threadIdx.x; e < 32*KNN; e += 256)
        sIdx[e] = idx[(size_t)(b*NN + i0)*KNN + e];
    __syncthreads();
    int o  = threadIdx.x & (O-1);
    int pp = threadIdx.x >> oshift;
    int PP = 256 >> oshift;
    float s1 = 0.f, s2 = 0.f;
    for (int ii = pp; ii < 32; ii += PP) {
        int gi = b*NN + i0 + ii;
        float qv = Q[(size_t)gi*ldq + o];
        float mx = -1e30f, mn = 1e30f;
        #pragma unroll 4
        for (int k = 0; k < KNN; k++) {
            int j = sIdx[ii*KNN + k];
            float v = P[(size_t)(b*NN + j)*ldp + o] + qv;
            s1 += v; s2 += v*v;
            mx = fmaxf(mx, v); mn = fminf(mn, v);
        }
        Mx[(size_t)gi*O + o] = mx;
        Mn[(size_t)gi*O + o] = mn;
    }
    red1[threadIdx.x] = s1; red2[threadIdx.x] = s2;
    __syncthreads();
    if (pp == 0) {
        for (int p = 1; p < PP; p++) { s1 += red1[o + p*O]; s2 += red2[o + p*O]; }
        int grp = blockIdx.y * gridDim.x + blockIdx.x;   // < 256
        part[(size_t)grp*O + o]         = s1;
        part[(size_t)(256 + grp)*O + o] = s2;
    }
}

__global__ void stats_plain(const float* __restrict__ P, float* __restrict__ part) {
    int b = blockIdx.y, i0 = blockIdx.x * 32;
    int o = threadIdx.x;  // 512
    float s1 = 0.f, s2 = 0.f;
    for (int ii = 0; ii < 32; ii++) {
        float v = P[(size_t)(b*NN + i0 + ii)*512 + o];
        s1 += v; s2 += v*v;
    }
    int grp = blockIdx.y * gridDim.x + blockIdx.x;
    part[(size_t)grp*512 + o]         = s1;
    part[(size_t)(256 + grp)*512 + o] = s2;
}

// warp-per-channel reduction over 256 groups. grid = O/8, block = 256.
__global__ void __launch_bounds__(256)
reduce_stats(int O, float cnt, const float* __restrict__ part,
             float* __restrict__ mean, float* __restrict__ istd) {
    int warp = threadIdx.x >> 5, lane = threadIdx.x & 31;
    int o = blockIdx.x*8 + warp;
    float s1 = 0.f, s2 = 0.f;
    #pragma unroll
    for (int g = lane; g < 256; g += 32) {
        s1 += part[(size_t)g*O + o];
        s2 += part[(size_t)(256 + g)*O + o];
    }
    #pragma unroll
    for (int off = 16; off; off >>= 1) {
        s1 += __shfl_down_sync(0xffffffffu, s1, off);
        s2 += __shfl_down_sync(0xffffffffu, s2, off);
    }
    if (lane == 0) {
        float m = s1 / cnt;
        float var = s2 / cnt - m*m;
        mean[o] = m;
        istd[o] = rsqrtf(var + EPS);
    }
}

// -------- elementwise finalize from max/min (monotone BN+lrelu) --------
__global__ void __launch_bounds__(256)
finalize_mm(const float* __restrict__ Mx, const float* __restrict__ Mn,
            int O, int oshift, int choff,
            const float* __restrict__ ga, const float* __restrict__ be,
            const float* __restrict__ mean, const float* __restrict__ istd,
            float* __restrict__ XCAT) {
    int base = blockIdx.x * 32 * O;
    for (int e = threadIdx.x; e < 32*O; e += 256) {
        int t = base + e;
        int o = t & (O-1);
        int gi = t >> oshift;
        float scale = istd[o] * ga[o];
        float v = (scale >= 0.f) ? Mx[t] : Mn[t];
        float z = (v - mean[o]) * scale + be[o];
        z = (z >= 0.f) ? z : NEG*z;
        XCAT[(size_t)gi*512 + choff + o] = z;
    }
}

// -------- final BN+lrelu with transposed write to d_out (B,512,N) --------
__global__ void finalize5(const float* __restrict__ P,
                          const float* __restrict__ ga, const float* __restrict__ be,
                          const float* __restrict__ mean, const float* __restrict__ istd,
                          float* __restrict__ out) {
    __shared__ float tile[32][33];
    int b = blockIdx.z, o0 = blockIdx.y * 32, n0 = blockIdx.x * 32;
    int tid = threadIdx.x;
    #pragma unroll
    for (int l = 0; l < 4; l++) {
        int e = tid + l*256;
        int nn = e >> 5, oo = e & 31;
        int o = o0 + oo;
        float v = P[(size_t)(b*NN + n0 + nn)*512 + o];
        v = (v - mean[o]) * istd[o] * ga[o] + be[o];
        v = (v >= 0.f) ? v : NEG*v;
        tile[oo][nn] = v;
    }
    __syncthreads();
    #pragma unroll
    for (int l = 0; l < 4; l++) {
        int e = tid + l*256;
        int oo = e >> 5, nn = e & 31;
        out[(size_t)b*512*NN + (size_t)(o0 + oo)*NN + n0 + nn] = tile[oo][nn];
    }
}

extern "C" void kernel_launch(void* const* d_in, const int* in_sizes, int n_in,
                              void* d_out, int out_size) {
    const float* x  = (const float*)d_in[0];
    const float* y  = (const float*)d_in[1];
    const float* w1 = (const float*)d_in[2];
    const float* w2 = (const float*)d_in[3];
    const float* w3 = (const float*)d_in[4];
    const float* w4 = (const float*)d_in[5];
    const float* w5 = (const float*)d_in[6];
    const float* g1 = (const float*)d_in[7];  const float* b1 = (const float*)d_in[8];
    const float* g2 = (const float*)d_in[9];  const float* b2 = (const float*)d_in[10];
    const float* g3 = (const float*)d_in[11]; const float* b3 = (const float*)d_in[12];
    const float* g4 = (const float*)d_in[13]; const float* b4 = (const float*)d_in[14];
    const float* g5 = (const float*)d_in[15]; const float* b5 = (const float*)d_in[16];
    float* out = (float*)d_out;

    float *X0, *yT, *ynT, *XCAT, *S, *P, *Q, *Wc, *cv, *part, *mean, *istd;
    int* idx;
    cudaGetSymbolAddress((void**)&X0,  g_X0);
    cudaGetSymbolAddress((void**)&yT,  g_yT);
    cudaGetSymbolAddress((void**)&ynT, g_ynT);
    cudaGetSymbolAddress((void**)&XCAT,g_XCAT);
    cudaGetSymbolAddress((void**)&S,   g_S);
    cudaGetSymbolAddress((void**)&P,   g_P);
    cudaGetSymbolAddress((void**)&Q,   g_Q);
    cudaGetSymbolAddress((void**)&Wc,  g_Wc);
    cudaGetSymbolAddress((void**)&cv,  g_cvec);
    cudaGetSymbolAddress((void**)&idx, g_idx);
    cudaGetSymbolAddress((void**)&part,g_part);
    cudaGetSymbolAddress((void**)&mean,g_mean);
    cudaGetSymbolAddress((void**)&istd,g_istd);

    float* Mx = S;                 // S is free outside score/topk windows
    float* Mn = S + (size_t)BN*256;

    transpose_x<<<(BN+255)/256, 256>>>(x, X0);
    prep_y<<<BN, 128>>>(y, yT, ynT);

    // ================= stage 1 : C=3 -> O=64, out slice [0,64) =================
    score1_topk<<<BN/8, 256>>>(X0, idx);
    make_wstack<<<(128*3+255)/256, 256>>>(w1, 64, 3, Wc);
    gemm128<<<dim3(1,64,1), 256>>>(3, 0, X0, 3, 0, Wc, 3, 0, nullptr, 0, P, 128, 0);
    stats_mm_edge<<<dim3(32,8), 256>>>(P, 128, P+64, 128, idx, 64, 6, part, Mx, Mn);
    reduce_stats<<<8, 256>>>(64, 163840.f, part, mean, istd);
    finalize_mm<<<BN/32, 256>>>(Mx, Mn, 64, 6, 0, g1, b1, mean, istd, XCAT);

    // ================= stage 2 : C=64 (x1 @ off 0) -> O=64, out [64,128) =======
    cvec_warp<<<BN/8, 256>>>(XCAT, 512, 64, cv);
    gemm128<<<dim3(8,8,8), 256>>>(64, 1, XCAT, 512, NN*512, XCAT, 512, NN*512, cv, NN, S, NN, NN*NN);
    topk_warp<<<BN/8, 256>>>(S, idx);
    make_wstack<<<(128*64+255)/256, 256>>>(w2, 64, 64, Wc);
    gemm128<<<dim3(1,64,1), 256>>>(64, 1, XCAT, 512, 0, Wc, 64, 0, nullptr, 0, P, 128, 0);
    stats_mm_edge<<<dim3(32,8), 256>>>(P, 128, P+64, 128, idx, 64, 6, part, Mx, Mn);
    reduce_stats<<<8, 256>>>(64, 163840.f, part, mean, istd);
    finalize_mm<<<BN/32, 256>>>(Mx, Mn, 64, 6, 64, g2, b2, mean, istd, XCAT);

    // ================= stage 3 : C=64 (x2 @ off 64) -> O=128, out [128,256) ====
    cvec_warp<<<BN/8, 256>>>(XCAT + 64, 512, 64, cv);
    gemm128<<<dim3(8,8,8), 256>>>(64, 1, XCAT + 64, 512, NN*512, XCAT + 64, 512, NN*512, cv, NN, S, NN, NN*NN);
    topk_warp<<<BN/8, 256>>>(S, idx);
    make_wstack<<<(256*64+255)/256, 256>>>(w3, 128, 64, Wc);
    gemm128<<<dim3(2,64,1), 256>>>(64, 1, XCAT + 64, 512, 0, Wc, 64, 0, nullptr, 0, P, 256, 0);
    stats_mm_edge<<<dim3(32,8), 256>>>(P, 256, P+128, 256, idx, 128, 7, part, Mx, Mn);
    reduce_stats<<<16, 256>>>(128, 163840.f, part, mean, istd);
    finalize_mm<<<BN/32, 256>>>(Mx, Mn, 128, 7, 128, g3, b3, mean, istd, XCAT);

    // ===== stage 4 : center x3 (C=128 @ off 128), source y -> O=256, out [256,512)
    gemm128<<<dim3(8,8,8), 256>>>(128, 1, XCAT + 128, 512, NN*512, ynT, 128, NN*128,
                                  nullptr, 0, S, NN, NN*NN);
    topk_warp<<<BN/8, 256>>>(S, idx);
    make_wc<<<(256*128+255)/256, 256>>>(w4, 256, 128, Wc);
    gemm128<<<dim3(2,64,1), 256>>>(128, 1, yT, 128, 0, w4, 256, 0, nullptr, 0, P, 256, 0);
    gemm128<<<dim3(2,64,1), 256>>>(128, 1, XCAT + 128, 512, 0, Wc, 128, 0, nullptr, 0, Q, 256, 0);
    stats_mm_edge<<<dim3(32,8), 256>>>(P, 256, Q, 256, idx, 256, 8, part, Mx, Mn);
    reduce_stats<<<32, 256>>>(256, 163840.f, part, mean, istd);
    finalize_mm<<<BN/32, 256>>>(Mx, Mn, 256, 8, 256, g4, b4, mean, istd, XCAT);

    // ================= stage 5 : 512 -> 512, BN over (B,N), write d_out ========
    gemm128<<<dim3(4,64,1), 256>>>(512, 1, XCAT, 512, 0, w5, 512, 0, nullptr, 0, P, 512, 0);
    stats_plain<<<dim3(32,8), 512>>>(P, part);
    reduce_stats<<<64, 256>>>(512, 8192.f, part, mean, istd);
    finalize5<<<dim3(32,16,8), 256>>>(P, g5, b5, mean, istd, out);
}

// round 6
// speedup vs baseline: 5.6452x; 1.0770x over previous
#include <cuda_runtime.h>
#include <math.h>

#define BB 8
#define NN 1024
#define BN (BB*NN)
#define KNN 20
#define NEG 0.2f
#define EPS 1e-5f

// weight regions inside g_Wc
#define WS1 0        // stacked w1: 128 x 3   (384)
#define WS2 512      // stacked w2: 128 x 64  (8192)
#define WS3 9216     // stacked w3: 256 x 64  (16384)
#define WS4 26112    // diff   w4: 256 x 128  (32768)  end=58880

// -------- scratch (device globals; no allocation allowed) --------
__device__ float g_X0[BN*3];          // x transposed (B,N,3)
__device__ float g_yT[BN*128];        // y transposed (B,M,128)
__device__ float g_ynT[BN*128];       // y normalized transposed
__device__ float g_XCAT[BN*512];      // concat of x1|x2|x3|x4 per point
__device__ float g_S[BB*NN*NN];       // score matrices (32MB); reused as Mx/Mn
__device__ float g_P[BN*512];         // PQ / stage5 pre-BN output
__device__ float g_Q[BN*256];         // stage4 Q
__device__ float g_Wc[64*1024];       // all prepped weights
__device__ int   g_idx[BN*KNN];       // knn indices
__device__ float g_part[2*512*512];   // BN partial sums
__device__ float g_mean[512];
__device__ float g_istd[512];

// -------- f32x2 packed helpers --------
__device__ __forceinline__ unsigned long long pack2(float x, float y) {
    unsigned long long r;
    asm("mov.b64 %0, {%1, %2};" : "=l"(r) : "f"(x), "f"(y));
    return r;
}
__device__ __forceinline__ void unpack2(unsigned long long v, float& x, float& y) {
    asm("mov.b64 {%0, %1}, %2;" : "=f"(x), "=f"(y) : "l"(v));
}
__device__ __forceinline__ void ffma2(unsigned long long& d,
                                      unsigned long long a, unsigned long long b) {
    asm("fma.rn.f32x2 %0, %1, %2, %0;" : "+l"(d) : "l"(a), "l"(b));
}

// -------- small prep kernels --------
__global__ void transpose_x(const float* __restrict__ x, float* __restrict__ X0) {
    int t = blockIdx.x*blockDim.x + threadIdx.x;
    if (t < BN) {
        int b = t >> 10, n = t & 1023;
        #pragma unroll
        for (int c = 0; c < 3; c++)
            X0[t*3 + c] = x[((size_t)b*3 + c)*NN + n];
    }
}

__global__ void prep_y(const float* __restrict__ y, float* __restrict__ yT,
                       float* __restrict__ ynT) {
    int m = blockIdx.x;            // global point 0..8191
    int b = m >> 10, mm = m & 1023;
    int c = threadIdx.x;           // 128
    float v = y[((size_t)b*128 + c)*NN + mm];
    __shared__ float red[128];
    red[c] = v*v;
    __syncthreads();
    for (int s = 64; s > 0; s >>= 1) {
        if (c < s) red[c] += red[c+s];
        __syncthreads();
    }
    float nrm = sqrtf(red[0]);
    float sc = 1.0f / fmaxf(nrm, 1e-12f);
    yT [(size_t)m*128 + c] = v;
    ynT[(size_t)m*128 + c] = v * sc;
}

// one kernel prepping all weights:
//   stacked: rows [0,O) = W[:, 0:C]; rows [O,2O) = W[:, C:2C] - W[:, 0:C]
//   diff only for w4
__global__ void make_weights(const float* __restrict__ w1, const float* __restrict__ w2,
                             const float* __restrict__ w3, const float* __restrict__ w4,
                             float* __restrict__ out) {
    int e = blockIdx.x*blockDim.x + threadIdx.x;
    // region 1: stacked w1, O=64 C=3 : 384
    if (e < 384) {
        int r = e / 3, c = e % 3;
        float v = (r < 64) ? w1[r*6 + c]
                           : w1[(r-64)*6 + 3 + c] - w1[(r-64)*6 + c];
        out[WS1 + e] = v;
    }
    // region 2: stacked w2, O=64 C=64 : 8192
    int e2 = e - 384;
    if (e2 >= 0 && e2 < 8192) {
        int r = e2 >> 6, c = e2 & 63;
        float v = (r < 64) ? w2[r*128 + c]
                           : w2[(r-64)*128 + 64 + c] - w2[(r-64)*128 + c];
        out[WS2 + e2] = v;
    }
    // region 3: stacked w3, O=128 C=64 : 16384
    int e3 = e2 - 8192;
    if (e3 >= 0 && e3 < 16384) {
        int r = e3 >> 6, c = e3 & 63;
        float v = (r < 128) ? w3[r*128 + c]
                            : w3[(r-128)*128 + 64 + c] - w3[(r-128)*128 + c];
        out[WS3 + e3] = v;
    }
    // region 4: diff w4, O=256 C=128 : 32768
    int e4 = e3 - 16384;
    if (e4 >= 0 && e4 < 32768) {
        int r = e4 >> 7, c = e4 & 127;
        out[WS4 + e4] = w4[r*256 + 128 + c] - w4[r*256 + c];
    }
}

// -------- GEMM: C[r][c] = sum_k A[r][k]*B[c][k] (+ selfbias: -0.5*|B_c|^2) ----
// 128x128 tile, 256 threads, 8x8 microtile, f32x2 FMA, double-buffered.
__global__ void __launch_bounds__(256, 2)
gemm128(int K, int vec, int selfbias,
        const float* __restrict__ A, int lda, int sA,
        const float* __restrict__ Bm, int ldb, int sB,
        float* __restrict__ C, int ldc, int sC) {
    __shared__ __align__(16) float As[2][16][132];
    __shared__ __align__(16) float Bs[2][16][132];
    int z = blockIdx.z;
    A  += (size_t)z * sA;
    Bm += (size_t)z * sB;
    C  += (size_t)z * sC;
    int row0 = blockIdx.y * 128, col0 = blockIdx.x * 128;
    int tid = threadIdx.x;
    int ty = tid >> 4, tx = tid & 15;

    unsigned long long acc[8][4];
    #pragma unroll
    for (int i = 0; i < 8; i++)
        #pragma unroll
        for (int j = 0; j < 4; j++) acc[i][j] = 0ULL;
    unsigned long long sq[4] = {0ULL, 0ULL, 0ULL, 0ULL};

    int nt = (K + 15) / 16;
    float ra[8], rb[8];
    float4 ra4[2], rb4[2];
    int vr = tid >> 2, vk = (tid & 3) * 4;

    if (vec) {
        #pragma unroll
        for (int l = 0; l < 2; l++) {
            ra4[l] = *(const float4*)&A [(size_t)(row0 + vr + l*64)*lda + vk];
            rb4[l] = *(const float4*)&Bm[(size_t)(col0 + vr + l*64)*ldb + vk];
        }
        #pragma unroll
        for (int l = 0; l < 2; l++) {
            int r = vr + l*64;
            As[0][vk+0][r] = ra4[l].x; As[0][vk+1][r] = ra4[l].y;
            As[0][vk+2][r] = ra4[l].z; As[0][vk+3][r] = ra4[l].w;
            Bs[0][vk+0][r] = rb4[l].x; Bs[0][vk+1][r] = rb4[l].y;
            Bs[0][vk+2][r] = rb4[l].z; Bs[0][vk+3][r] = rb4[l].w;
        }
    } else {
        #pragma unroll
        for (int l = 0; l < 8; l++) {
            int e = tid + l*256;
            int kk = e & 15, r = e >> 4;
            ra[l] = (kk < K) ? A [(size_t)(row0 + r)*lda + kk] : 0.f;
            rb[l] = (kk < K) ? Bm[(size_t)(col0 + r)*ldb + kk] : 0.f;
        }
        #pragma unroll
        for (int l = 0; l < 8; l++) {
            int e = tid + l*256;
            int kk = e & 15, r = e >> 4;
            As[0][kk][r] = ra[l];
            Bs[0][kk][r] = rb[l];
        }
    }
    __syncthreads();

    for (int t = 0; t < nt; t++) {
        int buf = t & 1;
        if (t + 1 < nt) {
            int k0 = (t + 1) * 16;
            if (vec) {
                #pragma unroll
                for (int l = 0; l < 2; l++) {
                    ra4[l] = *(const float4*)&A [(size_t)(row0 + vr + l*64)*lda + k0 + vk];
                    rb4[l] = *(const float4*)&Bm[(size_t)(col0 + vr + l*64)*ldb + k0 + vk];
                }
            } else {
                #pragma unroll
                for (int l = 0; l < 8; l++) {
                    int e = tid + l*256;
                    int kk = e & 15, r = e >> 4;
                    int gk = k0 + kk;
                    ra[l] = (gk < K) ? A [(size_t)(row0 + r)*lda + gk] : 0.f;
                    rb[l] = (gk < K) ? Bm[(size_t)(col0 + r)*ldb + gk] : 0.f;
                }
            }
        }
        #pragma unroll
        for (int kk = 0; kk < 16; kk++) {
            float4 a0 = *(const float4*)&As[buf][kk][ty*4];
            float4 a1 = *(const float4*)&As[buf][kk][ty*4 + 64];
            ulonglong2 bq0 = *(const ulonglong2*)&Bs[buf][kk][tx*4];
            ulonglong2 bq1 = *(const ulonglong2*)&Bs[buf][kk][tx*4 + 64];
            unsigned long long bb[4] = {bq0.x, bq0.y, bq1.x, bq1.y};
            float av[8] = {a0.x, a0.y, a0.z, a0.w, a1.x, a1.y, a1.z, a1.w};
            if (selfbias) {
                #pragma unroll
                for (int j = 0; j < 4; j++) ffma2(sq[j], bb[j], bb[j]);
            }
            #pragma unroll
            for (int i = 0; i < 8; i++) {
                unsigned long long ad = pack2(av[i], av[i]);
                #pragma unroll
                for (int j = 0; j < 4; j++) ffma2(acc[i][j], ad, bb[j]);
            }
        }
        if (t + 1 < nt) {
            int nb = (t + 1) & 1;
            if (vec) {
                #pragma unroll
                for (int l = 0; l < 2; l++) {
                    int r = vr + l*64;
                    As[nb][vk+0][r] = ra4[l].x; As[nb][vk+1][r] = ra4[l].y;
                    As[nb][vk+2][r] = ra4[l].z; As[nb][vk+3][r] = ra4[l].w;
                    Bs[nb][vk+0][r] = rb4[l].x; Bs[nb][vk+1][r] = rb4[l].y;
                    Bs[nb][vk+2][r] = rb4[l].z; Bs[nb][vk+3][r] = rb4[l].w;
                }
            } else {
                #pragma unroll
                for (int l = 0; l < 8; l++) {
                    int e = tid + l*256;
                    int kk = e & 15, r = e >> 4;
                    As[nb][kk][r] = ra[l];
                    Bs[nb][kk][r] = rb[l];
                }
            }
            __syncthreads();
        }
    }
    float bv[8] = {0,0,0,0,0,0,0,0};
    if (selfbias) {
        unpack2(sq[0], bv[0], bv[1]);
        unpack2(sq[1], bv[2], bv[3]);
        unpack2(sq[2], bv[4], bv[5]);
        unpack2(sq[3], bv[6], bv[7]);
        #pragma unroll
        for (int j = 0; j < 8; j++) bv[j] *= -0.5f;
    }
    #pragma unroll
    for (int i = 0; i < 8; i++) {
        int r = row0 + ((i >> 2) << 6) + ty*4 + (i & 3);
        int c0 = col0 + tx*4;
        int c1 = col0 + 64 + tx*4;
        float4 o0, o1;
        unpack2(acc[i][0], o0.x, o0.y);
        unpack2(acc[i][1], o0.z, o0.w);
        unpack2(acc[i][2], o1.x, o1.y);
        unpack2(acc[i][3], o1.z, o1.w);
        o0.x += bv[0]; o0.y += bv[1]; o0.z += bv[2]; o0.w += bv[3];
        o1.x += bv[4]; o1.y += bv[5]; o1.z += bv[6]; o1.w += bv[7];
        *(float4*)&C[(size_t)r*ldc + c0] = o0;
        *(float4*)&C[(size_t)r*ldc + c1] = o1;
    }
}

// -------- warp top-K over 32 register values per lane (column = j*32+lane) --------
__device__ __forceinline__ void warp_topk_regs(float (&v)[32], int r, int lane,
                                               int* __restrict__ out) {
    for (int k = 0; k < KNN; k++) {
        float tv16[16]; int tj16[16];
        #pragma unroll
        for (int j = 0; j < 16; j++) {
            bool t = v[2*j+1] > v[2*j];
            tv16[j] = t ? v[2*j+1] : v[2*j];
            tj16[j] = t ? 2*j+1 : 2*j;
        }
        float tv8[8]; int tj8[8];
        #pragma unroll
        for (int j = 0; j < 8; j++) {
            bool t = tv16[2*j+1] > tv16[2*j];
            tv8[j] = t ? tv16[2*j+1] : tv16[2*j];
            tj8[j] = t ? tj16[2*j+1] : tj16[2*j];
        }
        float tv4[4]; int tj4[4];
        #pragma unroll
        for (int j = 0; j < 4; j++) {
            bool t = tv8[2*j+1] > tv8[2*j];
            tv4[j] = t ? tv8[2*j+1] : tv8[2*j];
            tj4[j] = t ? tj8[2*j+1] : tj8[2*j];
        }
        float tv2[2]; int tj2[2];
        #pragma unroll
        for (int j = 0; j < 2; j++) {
            bool t = tv4[2*j+1] > tv4[2*j];
            tv2[j] = t ? tv4[2*j+1] : tv4[2*j];
            tj2[j] = t ? tj4[2*j+1] : tj4[2*j];
        }
        bool t0 = tv2[1] > tv2[0];
        float bv = t0 ? tv2[1] : tv2[0];
        int   bj = t0 ? tj2[1] : tj2[0];
        int   bg = bj*32 + lane;

        #pragma unroll
        for (int off = 16; off; off >>= 1) {
            float ov = __shfl_xor_sync(0xffffffffu, bv, off);
            int   og = __shfl_xor_sync(0xffffffffu, bg, off);
            if (ov > bv || (ov == bv && og < bg)) { bv = ov; bg = og; }
        }
        if (lane == 0) out[(size_t)r*KNN + k] = bg;

        int slot = bg >> 5;
        bool mine = (bg & 31) == lane;
        #pragma unroll
        for (int j = 0; j < 32; j++)
            if (mine && j == slot) v[j] = -1e30f;
    }
}

// -------- per-row top-K from a precomputed score matrix --------
__global__ void __launch_bounds__(256)
topk_warp(const float* __restrict__ S, int* __restrict__ out) {
    int warp = threadIdx.x >> 5, lane = threadIdx.x & 31;
    int r = blockIdx.x * 8 + warp;
    const float* row = S + (size_t)r * NN;
    float v[32];
    #pragma unroll
    for (int j = 0; j < 32; j++) v[j] = row[j*32 + lane];
    warp_topk_regs(v, r, lane, out);
}

// -------- stage 1 fused: compute xyz scores in regs + top-K (no S matrix) ----
__global__ void __launch_bounds__(256)
score1_topk(const float* __restrict__ X0, int* __restrict__ out) {
    int warp = threadIdx.x >> 5, lane = threadIdx.x & 31;
    int r = blockIdx.x * 8 + warp;          // global row (point i)
    int b = r >> 10;
    const float* Xb = X0 + (size_t)b * NN * 3;
    float cx = X0[(size_t)r*3+0], cy = X0[(size_t)r*3+1], cz = X0[(size_t)r*3+2];
    float v[32];
    #pragma unroll
    for (int j = 0; j < 32; j++) {
        int col = j*32 + lane;
        float xj = Xb[(size_t)col*3+0], yj = Xb[(size_t)col*3+1], zj = Xb[(size_t)col*3+2];
        float half = -0.5f * (xj*xj + yj*yj + zj*zj);
        v[j] = fmaf(cx, xj, fmaf(cy, yj, fmaf(cz, zj, half)));
    }
    warp_topk_regs(v, r, lane, out);
}

// -------- single gather pass: BN stats + per-(point,channel) max/min --------
// grid (64, BB), 16 points/block, 256 threads
__global__ void __launch_bounds__(256)
stats_mm_edge(const float* __restrict__ P, int ldp,
              const float* __restrict__ Q, int ldq,
              const int* __restrict__ idx, int O, int oshift,
              float* __restrict__ part,
              float* __restrict__ Mx, float* __restrict__ Mn) {
    __shared__ int sIdx[16*KNN];
    __shared__ float red1[256], red2[256];
    int b = blockIdx.y, i0 = blockIdx.x * 16;
    for (int e = threadIdx.x; e < 16*KNN; e += 256)
        sIdx[e] = idx[(size_t)(b*NN + i0)*KNN + e];
    __syncthreads();
    int o  = threadIdx.x & (O-1);
    int pp = threadIdx.x >> oshift;
    int PP = 256 >> oshift;
    float s1 = 0.f, s2 = 0.f;
    for (int ii = pp; ii < 16; ii += PP) {
        int gi = b*NN + i0 + ii;
        float qv = Q[(size_t)gi*ldq + o];
        float mx = -1e30f, mn = 1e30f;
        float pv[KNN];
        #pragma unroll
        for (int k = 0; k < KNN; k++) {
            int j = sIdx[ii*KNN + k];
            pv[k] = P[(size_t)(b*NN + j)*ldp + o];
        }
        #pragma unroll
        for (int k = 0; k < KNN; k++) {
            float v = pv[k] + qv;
            s1 += v; s2 += v*v;
            mx = fmaxf(mx, v); mn = fminf(mn, v);
        }
        Mx[(size_t)gi*O + o] = mx;
        Mn[(size_t)gi*O + o] = mn;
    }
    red1[threadIdx.x] = s1; red2[threadIdx.x] = s2;
    __syncthreads();
    if (pp == 0) {
        for (int p = 1; p < PP; p++) { s1 += red1[o + p*O]; s2 += red2[o + p*O]; }
        int grp = blockIdx.y * 64 + blockIdx.x;   // < 512
        part[(size_t)grp*O + o]         = s1;
        part[(size_t)(512 + grp)*O + o] = s2;
    }
}

// grid (64, BB), 512 threads, 16 points/block
__global__ void stats_plain(const float* __restrict__ P, float* __restrict__ part) {
    int b = blockIdx.y, i0 = blockIdx.x * 16;
    int o = threadIdx.x;  // 512
    float s1 = 0.f, s2 = 0.f;
    #pragma unroll
    for (int ii = 0; ii < 16; ii++) {
        float v = P[(size_t)(b*NN + i0 + ii)*512 + o];
        s1 += v; s2 += v*v;
    }
    int grp = blockIdx.y * 64 + blockIdx.x;
    part[(size_t)grp*512 + o]         = s1;
    part[(size_t)(512 + grp)*512 + o] = s2;
}

// warp-per-channel reduction over 512 groups. grid = O/8, block = 256.
__global__ void __launch_bounds__(256)
reduce_stats(int O, float cnt, const float* __restrict__ part,
             float* __restrict__ mean, float* __restrict__ istd) {
    int warp = threadIdx.x >> 5, lane = threadIdx.x & 31;
    int o = blockIdx.x*8 + warp;
    float s1 = 0.f, s2 = 0.f;
    #pragma unroll
    for (int g = lane; g < 512; g += 32) {
        s1 += part[(size_t)g*O + o];
        s2 += part[(size_t)(512 + g)*O + o];
    }
    #pragma unroll
    for (int off = 16; off; off >>= 1) {
        s1 += __shfl_down_sync(0xffffffffu, s1, off);
        s2 += __shfl_down_sync(0xffffffffu, s2, off);
    }
    if (lane == 0) {
        float m = s1 / cnt;
        float var = s2 / cnt - m*m;
        mean[o] = m;
        istd[o] = rsqrtf(var + EPS);
    }
}

// -------- vectorized finalize from max/min (monotone BN+lrelu) --------
// grid = BN*O/1024, block 256, each thread 1 float4
__global__ void __launch_bounds__(256)
finalize_mm4(const float4* __restrict__ Mx, const float4* __restrict__ Mn,
             int O, int oshift, int choff,
             const float4* __restrict__ ga, const float4* __restrict__ be,
             const float4* __restrict__ mean, const float4* __restrict__ istd,
             float* __restrict__ XCAT) {
    int t4 = blockIdx.x*256 + threadIdx.x;
    int gi = t4 >> (oshift - 2);
    int oq = t4 & ((O >> 2) - 1);
    float4 m = mean[oq], is = istd[oq], g = ga[oq], b = be[oq];
    float4 mx = Mx[t4], mn = Mn[t4];
    float4 r;
    {
        float sc = is.x * g.x; float v = (sc >= 0.f) ? mx.x : mn.x;
        float z = (v - m.x)*sc + b.x; r.x = (z >= 0.f) ? z : NEG*z;
    }
    {
        float sc = is.y * g.y; float v = (sc >= 0.f) ? mx.y : mn.y;
        float z = (v - m.y)*sc + b.y; r.y = (z >= 0.f) ? z : NEG*z;
    }
    {
        float sc = is.z * g.z; float v = (sc >= 0.f) ? mx.z : mn.z;
        float z = (v - m.z)*sc + b.z; r.z = (z >= 0.f) ? z : NEG*z;
    }
    {
        float sc = is.w * g.w; float v = (sc >= 0.f) ? mx.w : mn.w;
        float z = (v - m.w)*sc + b.w; r.w = (z >= 0.f) ? z : NEG*z;
    }
    *(float4*)&XCAT[(size_t)gi*512 + choff + oq*4] = r;
}

// -------- final BN+lrelu with transposed write to d_out (B,512,N) --------
__global__ void finalize5(const float* __restrict__ P,
                          const float* __restrict__ ga, const float* __restrict__ be,
                          const float* __restrict__ mean, const float* __restrict__ istd,
                          float* __restrict__ out) {
    __shared__ float tile[32][33];
    int b = blockIdx.z, o0 = blockIdx.y * 32, n0 = blockIdx.x * 32;
    int tid = threadIdx.x;
    #pragma unroll
    for (int l = 0; l < 4; l++) {
        int e = tid + l*256;
        int nn = e >> 5, oo = e & 31;
        int o = o0 + oo;
        float v = P[(size_t)(b*NN + n0 + nn)*512 + o];
        v = (v - mean[o]) * istd[o] * ga[o] + be[o];
        v = (v >= 0.f) ? v : NEG*v;
        tile[oo][nn] = v;
    }
    __syncthreads();
    #pragma unroll
    for (int l = 0; l < 4; l++) {
        int e = tid + l*256;
        int oo = e >> 5, nn = e & 31;
        out[(size_t)b*512*NN + (size_t)(o0 + oo)*NN + n0 + nn] = tile[oo][nn];
    }
}

extern "C" void kernel_launch(void* const* d_in, const int* in_sizes, int n_in,
                              void* d_out, int out_size) {
    const float* x  = (const float*)d_in[0];
    const float* y  = (const float*)d_in[1];
    const float* w1 = (const float*)d_in[2];
    const float* w2 = (const float*)d_in[3];
    const float* w3 = (const float*)d_in[4];
    const float* w4 = (const float*)d_in[5];
    const float* w5 = (const float*)d_in[6];
    const float* g1 = (const float*)d_in[7];  const float* b1 = (const float*)d_in[8];
    const float* g2 = (const float*)d_in[9];  const float* b2 = (const float*)d_in[10];
    const float* g3 = (const float*)d_in[11]; const float* b3 = (const float*)d_in[12];
    const float* g4 = (const float*)d_in[13]; const float* b4 = (const float*)d_in[14];
    const float* g5 = (const float*)d_in[15]; const float* b5 = (const float*)d_in[16];
    float* out = (float*)d_out;

    float *X0, *yT, *ynT, *XCAT, *S, *P, *Q, *Wc, *part, *mean, *istd;
    int* idx;
    cudaGetSymbolAddress((void**)&X0,  g_X0);
    cudaGetSymbolAddress((void**)&yT,  g_yT);
    cudaGetSymbolAddress((void**)&ynT, g_ynT);
    cudaGetSymbolAddress((void**)&XCAT,g_XCAT);
    cudaGetSymbolAddress((void**)&S,   g_S);
    cudaGetSymbolAddress((void**)&P,   g_P);
    cudaGetSymbolAddress((void**)&Q,   g_Q);
    cudaGetSymbolAddress((void**)&Wc,  g_Wc);
    cudaGetSymbolAddress((void**)&idx, g_idx);
    cudaGetSymbolAddress((void**)&part,g_part);
    cudaGetSymbolAddress((void**)&mean,g_mean);
    cudaGetSymbolAddress((void**)&istd,g_istd);

    float* Mx = S;                 // S is free outside score/topk windows
    float* Mn = S + (size_t)BN*256;

    transpose_x<<<(BN+255)/256, 256>>>(x, X0);
    prep_y<<<BN, 128>>>(y, yT, ynT);
    make_weights<<<226, 256>>>(w1, w2, w3, w4, Wc);

    // ================= stage 1 : C=3 -> O=64, out slice [0,64) =================
    score1_topk<<<BN/8, 256>>>(X0, idx);
    gemm128<<<dim3(1,64,1), 256>>>(3, 0, 0, X0, 3, 0, Wc+WS1, 3, 0, P, 128, 0);
    stats_mm_edge<<<dim3(64,8), 256>>>(P, 128, P+64, 128, idx, 64, 6, part, Mx, Mn);
    reduce_stats<<<8, 256>>>(64, 163840.f, part, mean, istd);
    finalize_mm4<<<BN*64/1024, 256>>>((float4*)Mx, (float4*)Mn, 64, 6, 0,
        (const float4*)g1, (const float4*)b1, (const float4*)mean, (const float4*)istd, XCAT);

    // ================= stage 2 : C=64 (x1 @ off 0) -> O=64, out [64,128) =======
    gemm128<<<dim3(8,8,8), 256>>>(64, 1, 1, XCAT, 512, NN*512, XCAT, 512, NN*512, S, NN, NN*NN);
    topk_warp<<<BN/8, 256>>>(S, idx);
    gemm128<<<dim3(1,64,1), 256>>>(64, 1, 0, XCAT, 512, 0, Wc+WS2, 64, 0, P, 128, 0);
    stats_mm_edge<<<dim3(64,8), 256>>>(P, 128, P+64, 128, idx, 64, 6, part, Mx, Mn);
    reduce_stats<<<8, 256>>>(64, 163840.f, part, mean, istd);
    finalize_mm4<<<BN*64/1024, 256>>>((float4*)Mx, (float4*)Mn, 64, 6, 64,
        (const float4*)g2, (const float4*)b2, (const float4*)mean, (const float4*)istd, XCAT);

    // ================= stage 3 : C=64 (x2 @ off 64) -> O=128, out [128,256) ====
    gemm128<<<dim3(8,8,8), 256>>>(64, 1, 1, XCAT + 64, 512, NN*512, XCAT + 64, 512, NN*512, S, NN, NN*NN);
    topk_warp<<<BN/8, 256>>>(S, idx);
    gemm128<<<dim3(2,64,1), 256>>>(64, 1, 0, XCAT + 64, 512, 0, Wc+WS3, 64, 0, P, 256, 0);
    stats_mm_edge<<<dim3(64,8), 256>>>(P, 256, P+128, 256, idx, 128, 7, part, Mx, Mn);
    reduce_stats<<<16, 256>>>(128, 163840.f, part, mean, istd);
    finalize_mm4<<<BN*128/1024, 256>>>((float4*)Mx, (float4*)Mn, 128, 7, 128,
        (const float4*)g3, (const float4*)b3, (const float4*)mean, (const float4*)istd, XCAT);

    // ===== stage 4 : center x3 (C=128 @ off 128), source y -> O=256, out [256,512)
    gemm128<<<dim3(8,8,8), 256>>>(128, 1, 0, XCAT + 128, 512, NN*512, ynT, 128, NN*128,
                                  S, NN, NN*NN);
    topk_warp<<<BN/8, 256>>>(S, idx);
    gemm128<<<dim3(2,64,1), 256>>>(128, 1, 0, yT, 128, 0, w4, 256, 0, P, 256, 0);
    gemm128<<<dim3(2,64,1), 256>>>(128, 1, 0, XCAT + 128, 512, 0, Wc+WS4, 128, 0, Q, 256, 0);
    stats_mm_edge<<<dim3(64,8), 256>>>(P, 256, Q, 256, idx, 256, 8, part, Mx, Mn);
    reduce_stats<<<32, 256>>>(256, 163840.f, part, mean, istd);
    finalize_mm4<<<BN*256/1024, 256>>>((float4*)Mx, (float4*)Mn, 256, 8, 256,
        (const float4*)g4, (const float4*)b4, (const float4*)mean, (const float4*)istd, XCAT);

    // ================= stage 5 : 512 -> 512, BN over (B,N), write d_out ========
    gemm128<<<dim3(4,64,1), 256>>>(512, 1, 0, XCAT, 512, 0, w5, 512, 0, P, 512, 0);
    stats_plain<<<dim3(64,8), 512>>>(P, part);
    reduce_stats<<<64, 256>>>(512, 8192.f, part, mean, istd);
    finalize5<<<dim3(32,16,8), 256>>>(P, g5, b5, mean, istd, out);
}

// round 7
// speedup vs baseline: 6.9708x; 1.2348x over previous
#include <cuda_runtime.h>
#include <math.h>

#define BB 8
#define NN 1024
#define BN (BB*NN)
#define KNN 20
#define NEG 0.2f
#define EPS 1e-5f
#define FULLM 0xffffffffu

// weight regions inside g_Wc
#define WS1 0        // stacked w1: 128 x 3   (384)
#define WS2 512      // stacked w2: 128 x 64  (8192)
#define WS3 9216     // stacked w3: 256 x 64  (16384)
#define WS4 26112    // diff   w4: 256 x 128  (32768)  end=58880

// -------- scratch (device globals; no allocation allowed) --------
__device__ float g_X0[BN*3];          // x transposed (B,N,3)
__device__ float g_yT[BN*128];        // y transposed (B,M,128)
__device__ float g_ynT[BN*128];       // y normalized transposed
__device__ float g_XCAT[BN*512];      // concat of x1|x2|x3|x4 per point
__device__ float g_S[BB*NN*NN];       // score matrices (32MB); reused as Mx/Mn
__device__ float g_P[BN*512];         // PQ / stage5 pre-BN output
__device__ float g_Q[BN*256];         // stage4 Q
__device__ float g_Wc[64*1024];       // all prepped weights
__device__ int   g_idx[BN*KNN];       // knn indices
__device__ float g_part[2*512*512];   // BN partial sums
__device__ float g_mean[512];
__device__ float g_istd[512];

// -------- f32x2 packed helpers --------
__device__ __forceinline__ unsigned long long pack2(float x, float y) {
    unsigned long long r;
    asm("mov.b64 %0, {%1, %2};" : "=l"(r) : "f"(x), "f"(y));
    return r;
}
__device__ __forceinline__ void unpack2(unsigned long long v, float& x, float& y) {
    asm("mov.b64 {%0, %1}, %2;" : "=f"(x), "=f"(y) : "l"(v));
}
__device__ __forceinline__ void ffma2(unsigned long long& d,
                                      unsigned long long a, unsigned long long b) {
    asm("fma.rn.f32x2 %0, %1, %2, %0;" : "+l"(d) : "l"(a), "l"(b));
}

// -------- small prep kernels --------
__global__ void transpose_x(const float* __restrict__ x, float* __restrict__ X0) {
    int t = blockIdx.x*blockDim.x + threadIdx.x;
    if (t < BN) {
        int b = t >> 10, n = t & 1023;
        #pragma unroll
        for (int c = 0; c < 3; c++)
            X0[t*3 + c] = x[((size_t)b*3 + c)*NN + n];
    }
}

__global__ void prep_y(const float* __restrict__ y, float* __restrict__ yT,
                       float* __restrict__ ynT) {
    int m = blockIdx.x;            // global point 0..8191
    int b = m >> 10, mm = m & 1023;
    int c = threadIdx.x;           // 128
    float v = y[((size_t)b*128 + c)*NN + mm];
    __shared__ float red[128];
    red[c] = v*v;
    __syncthreads();
    for (int s = 64; s > 0; s >>= 1) {
        if (c < s) red[c] += red[c+s];
        __syncthreads();
    }
    float nrm = sqrtf(red[0]);
    float sc = 1.0f / fmaxf(nrm, 1e-12f);
    yT [(size_t)m*128 + c] = v;
    ynT[(size_t)m*128 + c] = v * sc;
}

// one kernel prepping all weights
__global__ void make_weights(const float* __restrict__ w1, const float* __restrict__ w2,
                             const float* __restrict__ w3, const float* __restrict__ w4,
                             float* __restrict__ out) {
    int e = blockIdx.x*blockDim.x + threadIdx.x;
    if (e < 384) {
        int r = e / 3, c = e % 3;
        float v = (r < 64) ? w1[r*6 + c]
                           : w1[(r-64)*6 + 3 + c] - w1[(r-64)*6 + c];
        out[WS1 + e] = v;
    }
    int e2 = e - 384;
    if (e2 >= 0 && e2 < 8192) {
        int r = e2 >> 6, c = e2 & 63;
        float v = (r < 64) ? w2[r*128 + c]
                           : w2[(r-64)*128 + 64 + c] - w2[(r-64)*128 + c];
        out[WS2 + e2] = v;
    }
    int e3 = e2 - 8192;
    if (e3 >= 0 && e3 < 16384) {
        int r = e3 >> 6, c = e3 & 63;
        float v = (r < 128) ? w3[r*128 + c]
                            : w3[(r-128)*128 + 64 + c] - w3[(r-128)*128 + c];
        out[WS3 + e3] = v;
    }
    int e4 = e3 - 16384;
    if (e4 >= 0 && e4 < 32768) {
        int r = e4 >> 7, c = e4 & 127;
        out[WS4 + e4] = w4[r*256 + 128 + c] - w4[r*256 + c];
    }
}

// -------- GEMM: C[r][c] = sum_k A[r][k]*B[c][k] (+ selfbias: -0.5*|B_c|^2) ----
__global__ void __launch_bounds__(256, 2)
gemm128(int K, int vec, int selfbias,
        const float* __restrict__ A, int lda, int sA,
        const float* __restrict__ Bm, int ldb, int sB,
        float* __restrict__ C, int ldc, int sC) {
    __shared__ __align__(16) float As[2][16][132];
    __shared__ __align__(16) float Bs[2][16][132];
    int z = blockIdx.z;
    A  += (size_t)z * sA;
    Bm += (size_t)z * sB;
    C  += (size_t)z * sC;
    int row0 = blockIdx.y * 128, col0 = blockIdx.x * 128;
    int tid = threadIdx.x;
    int ty = tid >> 4, tx = tid & 15;

    unsigned long long acc[8][4];
    #pragma unroll
    for (int i = 0; i < 8; i++)
        #pragma unroll
        for (int j = 0; j < 4; j++) acc[i][j] = 0ULL;
    unsigned long long sq[4] = {0ULL, 0ULL, 0ULL, 0ULL};

    int nt = (K + 15) / 16;
    float ra[8], rb[8];
    float4 ra4[2], rb4[2];
    int vr = tid >> 2, vk = (tid & 3) * 4;

    if (vec) {
        #pragma unroll
        for (int l = 0; l < 2; l++) {
            ra4[l] = *(const float4*)&A [(size_t)(row0 + vr + l*64)*lda + vk];
            rb4[l] = *(const float4*)&Bm[(size_t)(col0 + vr + l*64)*ldb + vk];
        }
        #pragma unroll
        for (int l = 0; l < 2; l++) {
            int r = vr + l*64;
            As[0][vk+0][r] = ra4[l].x; As[0][vk+1][r] = ra4[l].y;
            As[0][vk+2][r] = ra4[l].z; As[0][vk+3][r] = ra4[l].w;
            Bs[0][vk+0][r] = rb4[l].x; Bs[0][vk+1][r] = rb4[l].y;
            Bs[0][vk+2][r] = rb4[l].z; Bs[0][vk+3][r] = rb4[l].w;
        }
    } else {
        #pragma unroll
        for (int l = 0; l < 8; l++) {
            int e = tid + l*256;
            int kk = e & 15, r = e >> 4;
            ra[l] = (kk < K) ? A [(size_t)(row0 + r)*lda + kk] : 0.f;
            rb[l] = (kk < K) ? Bm[(size_t)(col0 + r)*ldb + kk] : 0.f;
        }
        #pragma unroll
        for (int l = 0; l < 8; l++) {
            int e = tid + l*256;
            int kk = e & 15, r = e >> 4;
            As[0][kk][r] = ra[l];
            Bs[0][kk][r] = rb[l];
        }
    }
    __syncthreads();

    for (int t = 0; t < nt; t++) {
        int buf = t & 1;
        if (t + 1 < nt) {
            int k0 = (t + 1) * 16;
            if (vec) {
                #pragma unroll
                for (int l = 0; l < 2; l++) {
                    ra4[l] = *(const float4*)&A [(size_t)(row0 + vr + l*64)*lda + k0 + vk];
                    rb4[l] = *(const float4*)&Bm[(size_t)(col0 + vr + l*64)*ldb + k0 + vk];
                }
            } else {
                #pragma unroll
                for (int l = 0; l < 8; l++) {
                    int e = tid + l*256;
                    int kk = e & 15, r = e >> 4;
                    int gk = k0 + kk;
                    ra[l] = (gk < K) ? A [(size_t)(row0 + r)*lda + gk] : 0.f;
                    rb[l] = (gk < K) ? Bm[(size_t)(col0 + r)*ldb + gk] : 0.f;
                }
            }
        }
        #pragma unroll
        for (int kk = 0; kk < 16; kk++) {
            float4 a0 = *(const float4*)&As[buf][kk][ty*4];
            float4 a1 = *(const float4*)&As[buf][kk][ty*4 + 64];
            ulonglong2 bq0 = *(const ulonglong2*)&Bs[buf][kk][tx*4];
            ulonglong2 bq1 = *(const ulonglong2*)&Bs[buf][kk][tx*4 + 64];
            unsigned long long bb[4] = {bq0.x, bq0.y, bq1.x, bq1.y};
            float av[8] = {a0.x, a0.y, a0.z, a0.w, a1.x, a1.y, a1.z, a1.w};
            if (selfbias) {
                #pragma unroll
                for (int j = 0; j < 4; j++) ffma2(sq[j], bb[j], bb[j]);
            }
            #pragma unroll
            for (int i = 0; i < 8; i++) {
                unsigned long long ad = pack2(av[i], av[i]);
                #pragma unroll
                for (int j = 0; j < 4; j++) ffma2(acc[i][j], ad, bb[j]);
            }
        }
        if (t + 1 < nt) {
            int nb = (t + 1) & 1;
            if (vec) {
                #pragma unroll
                for (int l = 0; l < 2; l++) {
                    int r = vr + l*64;
                    As[nb][vk+0][r] = ra4[l].x; As[nb][vk+1][r] = ra4[l].y;
                    As[nb][vk+2][r] = ra4[l].z; As[nb][vk+3][r] = ra4[l].w;
                    Bs[nb][vk+0][r] = rb4[l].x; Bs[nb][vk+1][r] = rb4[l].y;
                    Bs[nb][vk+2][r] = rb4[l].z; Bs[nb][vk+3][r] = rb4[l].w;
                }
            } else {
                #pragma unroll
                for (int l = 0; l < 8; l++) {
                    int e = tid + l*256;
                    int kk = e & 15, r = e >> 4;
                    As[nb][kk][r] = ra[l];
                    Bs[nb][kk][r] = rb[l];
                }
            }
            __syncthreads();
        }
    }
    float bv[8] = {0,0,0,0,0,0,0,0};
    if (selfbias) {
        unpack2(sq[0], bv[0], bv[1]);
        unpack2(sq[1], bv[2], bv[3]);
        unpack2(sq[2], bv[4], bv[5]);
        unpack2(sq[3], bv[6], bv[7]);
        #pragma unroll
        for (int j = 0; j < 8; j++) bv[j] *= -0.5f;
    }
    #pragma unroll
    for (int i = 0; i < 8; i++) {
        int r = row0 + ((i >> 2) << 6) + ty*4 + (i & 3);
        int c0 = col0 + tx*4;
        int c1 = col0 + 64 + tx*4;
        float4 o0, o1;
        unpack2(acc[i][0], o0.x, o0.y);
        unpack2(acc[i][1], o0.z, o0.w);
        unpack2(acc[i][2], o1.x, o1.y);
        unpack2(acc[i][3], o1.z, o1.w);
        o0.x += bv[0]; o0.y += bv[1]; o0.z += bv[2]; o0.w += bv[3];
        o1.x += bv[4]; o1.y += bv[5]; o1.z += bv[6]; o1.w += bv[7];
        *(float4*)&C[(size_t)r*ldc + c0] = o0;
        *(float4*)&C[(size_t)r*ldc + c1] = o1;
    }
}

// -------- warp top-20 via multi-admission bitonic rounds --------
// Lane holds 32 values; column of v[j] = j*32 + lane. Expected ~3 rounds.
__device__ __forceinline__ void warp_topk20(float (&v)[32], int r, int lane,
                                            int* __restrict__ out) {
    int done = 0;
    while (done < KNN) {
        // ---- per-lane head (value + slot), ties -> lower slot ----
        float tv16[16]; int tj16[16];
        #pragma unroll
        for (int j = 0; j < 16; j++) {
            bool t = v[2*j+1] > v[2*j];
            tv16[j] = t ? v[2*j+1] : v[2*j];
            tj16[j] = t ? 2*j+1 : 2*j;
        }
        float tv8[8]; int tj8[8];
        #pragma unroll
        for (int j = 0; j < 8; j++) {
            bool t = tv16[2*j+1] > tv16[2*j];
            tv8[j] = t ? tv16[2*j+1] : tv16[2*j];
            tj8[j] = t ? tj16[2*j+1] : tj16[2*j];
        }
        float tv4[4]; int tj4[4];
        #pragma unroll
        for (int j = 0; j < 4; j++) {
            bool t = tv8[2*j+1] > tv8[2*j];
            tv4[j] = t ? tv8[2*j+1] : tv8[2*j];
            tj4[j] = t ? tj8[2*j+1] : tj8[2*j];
        }
        float tv2[2]; int tj2[2];
        #pragma unroll
        for (int j = 0; j < 2; j++) {
            bool t = tv4[2*j+1] > tv4[2*j];
            tv2[j] = t ? tv4[2*j+1] : tv4[2*j];
            tj2[j] = t ? tj4[2*j+1] : tj4[2*j];
        }
        bool t0 = tv2[1] > tv2[0];
        float h  = t0 ? tv2[1] : tv2[0];   // my head value
        int   hs = t0 ? tj2[1] : tj2[0];   // my head slot

        // ---- per-lane second (max of values strictly below head) ----
        float s = -INFINITY;
        #pragma unroll
        for (int j = 0; j < 32; j++) {
            float t = (v[j] < h) ? v[j] : -INFINITY;
            s = fmaxf(s, t);
        }

        // ---- bitonic sort (head, srclane) ascending across warp ----
        float hh = h;
        int   sl = lane;
        #pragma unroll
        for (int k = 2; k <= 32; k <<= 1) {
            #pragma unroll
            for (int j = k >> 1; j > 0; j >>= 1) {
                float oh = __shfl_xor_sync(FULLM, hh, j);
                int   ol = __shfl_xor_sync(FULLM, sl, j);
                bool up = ((lane & k) == 0);
                bool oless = (oh < hh) || (oh == hh && ol < sl);
                bool takeMin = (((lane & j) == 0) == up);
                bool pick_o = (oless == takeMin);
                hh = pick_o ? oh : hh;
                sl = pick_o ? ol : sl;
            }
        }
        int di = 31 - lane;               // descending rank of my sorted head

        // seconds routed to sorted order
        float ssrt = __shfl_sync(FULLM, s, sl);
        // exclusive prefix-max (over smaller di == larger lanes)
        float t1 = __shfl_down_sync(FULLM, ssrt, 1);
        float pm = (lane == 31) ? -INFINITY : t1;
        #pragma unroll
        for (int off = 1; off < 32; off <<= 1) {
            float t = __shfl_down_sync(FULLM, pm, off);
            pm = fmaxf(pm, t);            // OOB shfl returns own value -> harmless
        }

        int need = KNN - done;
        bool iadm = (hh > pm) && (di < need);
        unsigned admmask = __ballot_sync(FULLM, iadm);
        int cnt = __popc(admmask);

        // global column index of the admitted head (fetch src lane's slot)
        int hsl = __shfl_sync(FULLM, hs, sl);
        int g   = hsl * 32 + sl;
        if (iadm) out[(size_t)r*KNN + done + di] = g;

        // tell source lanes to clear their consumed head
        unsigned m = iadm ? (1u << sl) : 0u;
        #pragma unroll
        for (int off = 16; off; off >>= 1)
            m |= __shfl_xor_sync(FULLM, m, off);
        bool clearme = (m >> lane) & 1u;
        #pragma unroll
        for (int j = 0; j < 32; j++)
            if (clearme && j == hs) v[j] = -INFINITY;

        done += cnt;
    }
}

// -------- per-row top-K from a precomputed score matrix --------
__global__ void __launch_bounds__(256)
topk_warp(const float* __restrict__ S, int* __restrict__ out) {
    int warp = threadIdx.x >> 5, lane = threadIdx.x & 31;
    int r = blockIdx.x * 8 + warp;
    const float* row = S + (size_t)r * NN;
    float v[32];
    #pragma unroll
    for (int j = 0; j < 32; j++) v[j] = row[j*32 + lane];
    warp_topk20(v, r, lane, out);
}

// -------- stage 1 fused: compute xyz scores in regs + top-K (no S matrix) ----
__global__ void __launch_bounds__(256)
score1_topk(const float* __restrict__ X0, int* __restrict__ out) {
    int warp = threadIdx.x >> 5, lane = threadIdx.x & 31;
    int r = blockIdx.x * 8 + warp;          // global row (point i)
    int b = r >> 10;
    const float* Xb = X0 + (size_t)b * NN * 3;
    float cx = X0[(size_t)r*3+0], cy = X0[(size_t)r*3+1], cz = X0[(size_t)r*3+2];
    float v[32];
    #pragma unroll
    for (int j = 0; j < 32; j++) {
        int col = j*32 + lane;
        float xj = Xb[(size_t)col*3+0], yj = Xb[(size_t)col*3+1], zj = Xb[(size_t)col*3+2];
        float half = -0.5f * (xj*xj + yj*yj + zj*zj);
        v[j] = fmaf(cx, xj, fmaf(cy, yj, fmaf(cz, zj, half)));
    }
    warp_topk20(v, r, lane, out);
}

// -------- single gather pass: BN stats + per-(point,channel) max/min --------
__global__ void __launch_bounds__(256)
stats_mm_edge(const float* __restrict__ P, int ldp,
              const float* __restrict__ Q, int ldq,
              const int* __restrict__ idx, int O, int oshift,
              float* __restrict__ part,
              float* __restrict__ Mx, float* __restrict__ Mn) {
    __shared__ int sIdx[16*KNN];
    __shared__ float red1[256], red2[256];
    int b = blockIdx.y, i0 = blockIdx.x * 16;
    for (int e = threadIdx.x; e < 16*KNN; e += 256)
        sIdx[e] = idx[(size_t)(b*NN + i0)*KNN + e];
    __syncthreads();
    int o  = threadIdx.x & (O-1);
    int pp = threadIdx.x >> oshift;
    int PP = 256 >> oshift;
    float s1 = 0.f, s2 = 0.f;
    for (int ii = pp; ii < 16; ii += PP) {
        int gi = b*NN + i0 + ii;
        float qv = Q[(size_t)gi*ldq + o];
        float mx = -1e30f, mn = 1e30f;
        float pv[KNN];
        #pragma unroll
        for (int k = 0; k < KNN; k++) {
            int j = sIdx[ii*KNN + k];
            pv[k] = P[(size_t)(b*NN + j)*ldp + o];
        }
        #pragma unroll
        for (int k = 0; k < KNN; k++) {
            float v = pv[k] + qv;
            s1 += v; s2 += v*v;
            mx = fmaxf(mx, v); mn = fminf(mn, v);
        }
        Mx[(size_t)gi*O + o] = mx;
        Mn[(size_t)gi*O + o] = mn;
    }
    red1[threadIdx.x] = s1; red2[threadIdx.x] = s2;
    __syncthreads();
    if (pp == 0) {
        for (int p = 1; p < PP; p++) { s1 += red1[o + p*O]; s2 += red2[o + p*O]; }
        int grp = blockIdx.y * 64 + blockIdx.x;   // < 512
        part[(size_t)grp*O + o]         = s1;
        part[(size_t)(512 + grp)*O + o] = s2;
    }
}

__global__ void stats_plain(const float* __restrict__ P, float* __restrict__ part) {
    int b = blockIdx.y, i0 = blockIdx.x * 16;
    int o = threadIdx.x;  // 512
    float s1 = 0.f, s2 = 0.f;
    #pragma unroll
    for (int ii = 0; ii < 16; ii++) {
        float v = P[(size_t)(b*NN + i0 + ii)*512 + o];
        s1 += v; s2 += v*v;
    }
    int grp = blockIdx.y * 64 + blockIdx.x;
    part[(size_t)grp*512 + o]         = s1;
    part[(size_t)(512 + grp)*512 + o] = s2;
}

// warp-per-channel reduction over 512 groups. grid = O/8, block = 256.
__global__ void __launch_bounds__(256)
reduce_stats(int O, float cnt, const float* __restrict__ part,
             float* __restrict__ mean, float* __restrict__ istd) {
    int warp = threadIdx.x >> 5, lane = threadIdx.x & 31;
    int o = blockIdx.x*8 + warp;
    float s1 = 0.f, s2 = 0.f;
    #pragma unroll
    for (int g = lane; g < 512; g += 32) {
        s1 += part[(size_t)g*O + o];
        s2 += part[(size_t)(512 + g)*O + o];
    }
    #pragma unroll
    for (int off = 16; off; off >>= 1) {
        s1 += __shfl_down_sync(FULLM, s1, off);
        s2 += __shfl_down_sync(FULLM, s2, off);
    }
    if (lane == 0) {
        float m = s1 / cnt;
        float var = s2 / cnt - m*m;
        mean[o] = m;
        istd[o] = rsqrtf(var + EPS);
    }
}

// -------- vectorized finalize from max/min (monotone BN+lrelu) --------
__global__ void __launch_bounds__(256)
finalize_mm4(const float4* __restrict__ Mx, const float4* __restrict__ Mn,
             int O, int oshift, int choff,
             const float4* __restrict__ ga, const float4* __restrict__ be,
             const float4* __restrict__ mean, const float4* __restrict__ istd,
             float* __restrict__ XCAT) {
    int t4 = blockIdx.x*256 + threadIdx.x;
    int gi = t4 >> (oshift - 2);
    int oq = t4 & ((O >> 2) - 1);
    float4 m = mean[oq], is = istd[oq], g = ga[oq], b = be[oq];
    float4 mx = Mx[t4], mn = Mn[t4];
    float4 r;
    {
        float sc = is.x * g.x; float v = (sc >= 0.f) ? mx.x : mn.x;
        float z = (v - m.x)*sc + b.x; r.x = (z >= 0.f) ? z : NEG*z;
    }
    {
        float sc = is.y * g.y; float v = (sc >= 0.f) ? mx.y : mn.y;
        float z = (v - m.y)*sc + b.y; r.y = (z >= 0.f) ? z : NEG*z;
    }
    {
        float sc = is.z * g.z; float v = (sc >= 0.f) ? mx.z : mn.z;
        float z = (v - m.z)*sc + b.z; r.z = (z >= 0.f) ? z : NEG*z;
    }
    {
        float sc = is.w * g.w; float v = (sc >= 0.f) ? mx.w : mn.w;
        float z = (v - m.w)*sc + b.w; r.w = (z >= 0.f) ? z : NEG*z;
    }
    *(float4*)&XCAT[(size_t)gi*512 + choff + oq*4] = r;
}

// -------- final BN+lrelu with transposed write to d_out (B,512,N) --------
__global__ void finalize5(const float* __restrict__ P,
                          const float* __restrict__ ga, const float* __restrict__ be,
                          const float* __restrict__ mean, const float* __restrict__ istd,
                          float* __restrict__ out) {
    __shared__ float tile[32][33];
    int b = blockIdx.z, o0 = blockIdx.y * 32, n0 = blockIdx.x * 32;
    int tid = threadIdx.x;
    #pragma unroll
    for (int l = 0; l < 4; l++) {
        int e = tid + l*256;
        int nn = e >> 5, oo = e & 31;
        int o = o0 + oo;
        float v = P[(size_t)(b*NN + n0 + nn)*512 + o];
        v = (v - mean[o]) * istd[o] * ga[o] + be[o];
        v = (v >= 0.f) ? v : NEG*v;
        tile[oo][nn] = v;
    }
    __syncthreads();
    #pragma unroll
    for (int l = 0; l < 4; l++) {
        int e = tid + l*256;
        int oo = e >> 5, nn = e & 31;
        out[(size_t)b*512*NN + (size_t)(o0 + oo)*NN + n0 + nn] = tile[oo][nn];
    }
}

extern "C" void kernel_launch(void* const* d_in, const int* in_sizes, int n_in,
                              void* d_out, int out_size) {
    const float* x  = (const float*)d_in[0];
    const float* y  = (const float*)d_in[1];
    const float* w1 = (const float*)d_in[2];
    const float* w2 = (const float*)d_in[3];
    const float* w3 = (const float*)d_in[4];
    const float* w4 = (const float*)d_in[5];
    const float* w5 = (const float*)d_in[6];
    const float* g1 = (const float*)d_in[7];  const float* b1 = (const float*)d_in[8];
    const float* g2 = (const float*)d_in[9];  const float* b2 = (const float*)d_in[10];
    const float* g3 = (const float*)d_in[11]; const float* b3 = (const float*)d_in[12];
    const float* g4 = (const float*)d_in[13]; const float* b4 = (const float*)d_in[14];
    const float* g5 = (const float*)d_in[15]; const float* b5 = (const float*)d_in[16];
    float* out = (float*)d_out;

    float *X0, *yT, *ynT, *XCAT, *S, *P, *Q, *Wc, *part, *mean, *istd;
    int* idx;
    cudaGetSymbolAddress((void**)&X0,  g_X0);
    cudaGetSymbolAddress((void**)&yT,  g_yT);
    cudaGetSymbolAddress((void**)&ynT, g_ynT);
    cudaGetSymbolAddress((void**)&XCAT,g_XCAT);
    cudaGetSymbolAddress((void**)&S,   g_S);
    cudaGetSymbolAddress((void**)&P,   g_P);
    cudaGetSymbolAddress((void**)&Q,   g_Q);
    cudaGetSymbolAddress((void**)&Wc,  g_Wc);
    cudaGetSymbolAddress((void**)&idx, g_idx);
    cudaGetSymbolAddress((void**)&part,g_part);
    cudaGetSymbolAddress((void**)&mean,g_mean);
    cudaGetSymbolAddress((void**)&istd,g_istd);

    float* Mx = S;                 // S is free outside score/topk windows
    float* Mn = S + (size_t)BN*256;

    transpose_x<<<(BN+255)/256, 256>>>(x, X0);
    prep_y<<<BN, 128>>>(y, yT, ynT);
    make_weights<<<226, 256>>>(w1, w2, w3, w4, Wc);

    // ================= stage 1 : C=3 -> O=64, out slice [0,64) =================
    score1_topk<<<BN/8, 256>>>(X0, idx);
    gemm128<<<dim3(1,64,1), 256>>>(3, 0, 0, X0, 3, 0, Wc+WS1, 3, 0, P, 128, 0);
    stats_mm_edge<<<dim3(64,8), 256>>>(P, 128, P+64, 128, idx, 64, 6, part, Mx, Mn);
    reduce_stats<<<8, 256>>>(64, 163840.f, part, mean, istd);
    finalize_mm4<<<BN*64/1024, 256>>>((float4*)Mx, (float4*)Mn, 64, 6, 0,
        (const float4*)g1, (const float4*)b1, (const float4*)mean, (const float4*)istd, XCAT);

    // ================= stage 2 : C=64 (x1 @ off 0) -> O=64, out [64,128) =======
    gemm128<<<dim3(8,8,8), 256>>>(64, 1, 1, XCAT, 512, NN*512, XCAT, 512, NN*512, S, NN, NN*NN);
    topk_warp<<<BN/8, 256>>>(S, idx);
    gemm128<<<dim3(1,64,1), 256>>>(64, 1, 0, XCAT, 512, 0, Wc+WS2, 64, 0, P, 128, 0);
    stats_mm_edge<<<dim3(64,8), 256>>>(P, 128, P+64, 128, idx, 64, 6, part, Mx, Mn);
    reduce_stats<<<8, 256>>>(64, 163840.f, part, mean, istd);
    finalize_mm4<<<BN*64/1024, 256>>>((float4*)Mx, (float4*)Mn, 64, 6, 64,
        (const float4*)g2, (const float4*)b2, (const float4*)mean, (const float4*)istd, XCAT);

    // ================= stage 3 : C=64 (x2 @ off 64) -> O=128, out [128,256) ====
    gemm128<<<dim3(8,8,8), 256>>>(64, 1, 1, XCAT + 64, 512, NN*512, XCAT + 64, 512, NN*512, S, NN, NN*NN);
    topk_warp<<<BN/8, 256>>>(S, idx);
    gemm128<<<dim3(2,64,1), 256>>>(64, 1, 0, XCAT + 64, 512, 0, Wc+WS3, 64, 0, P, 256, 0);
    stats_mm_edge<<<dim3(64,8), 256>>>(P, 256, P+128, 256, idx, 128, 7, part, Mx, Mn);
    reduce_stats<<<16, 256>>>(128, 163840.f, part, mean, istd);
    finalize_mm4<<<BN*128/1024, 256>>>((float4*)Mx, (float4*)Mn, 128, 7, 128,
        (const float4*)g3, (const float4*)b3, (const float4*)mean, (const float4*)istd, XCAT);

    // ===== stage 4 : center x3 (C=128 @ off 128), source y -> O=256, out [256,512)
    gemm128<<<dim3(8,8,8), 256>>>(128, 1, 0, XCAT + 128, 512, NN*512, ynT, 128, NN*128,
                                  S, NN, NN*NN);
    topk_warp<<<BN/8, 256>>>(S, idx);
    gemm128<<<dim3(2,64,1), 256>>>(128, 1, 0, yT, 128, 0, w4, 256, 0, P, 256, 0);
    gemm128<<<dim3(2,64,1), 256>>>(128, 1, 0, XCAT + 128, 512, 0, Wc+WS4, 128, 0, Q, 256, 0);
    stats_mm_edge<<<dim3(64,8), 256>>>(P, 256, Q, 256, idx, 256, 8, part, Mx, Mn);
    reduce_stats<<<32, 256>>>(256, 163840.f, part, mean, istd);
    finalize_mm4<<<BN*256/1024, 256>>>((float4*)Mx, (float4*)Mn, 256, 8, 256,
        (const float4*)g4, (const float4*)b4, (const float4*)mean, (const float4*)istd, XCAT);

    // ================= stage 5 : 512 -> 512, BN over (B,N), write d_out ========
    gemm128<<<dim3(4,64,1), 256>>>(512, 1, 0, XCAT, 512, 0, w5, 512, 0, P, 512, 0);
    stats_plain<<<dim3(64,8), 512>>>(P, part);
    reduce_stats<<<64, 256>>>(512, 8192.f, part, mean, istd);
    finalize5<<<dim3(32,16,8), 256>>>(P, g5, b5, mean, istd, out);
}